// round 12
// baseline (speedup 1.0000x reference)
#include <cuda_runtime.h>
#include <cuda_fp16.h>
#include <cstdint>

#define N_NODES  131072
#define N_EDGES  2097152
#define F_IN     32
#define HID      64
#define G_FEAT   16
#define N_GRAPHS 1024
#define BN_EPS   1e-5f
#define SRT_CAP  (N_EDGES + 8 * N_NODES)

// ---------------- device scratch (zero-initialized at load; recycled each run) --------
__device__ int   g_degi[N_NODES];          // zeroed by poolmlp (end of each run)
__device__ int   g_rowstart[N_NODES];
__device__ int   g_rank[N_EDGES];          // per-edge insertion rank (from deg atomics)
__device__ int   g_srt[SRT_CAP];
__device__ unsigned long long g_scanstat[512];  // zeroed by poolmlp
__device__ float g_dinv[N_NODES];
// +1 dummy zero row at index N_NODES (never written; stays zero)
__device__ __align__(16) __half2 g_y1[(size_t)(N_NODES + 1) * 16];  // dinv*x (32 feats)
__device__ __align__(16) __half2 g_a1[(size_t)N_NODES * 16];        // dinv*agg(y1)
__device__ __align__(16) __half2 g_z1[(size_t)N_NODES * 32];        // a1@W1+b1
__device__ __align__(16) __half2 g_y2[(size_t)(N_NODES + 1) * 32];  // dinv*relu(bn(z1))
__device__ __align__(16) __half2 g_a2[(size_t)N_NODES * 32];        // dinv*agg(y2)
__device__ __align__(16) __half2 g_z2[(size_t)N_NODES * 32];        // a2@W2+b2
__device__ float g_s1[HID], g_q1[HID];     // reset by agg2 (after prep2 reads them)
__device__ float g_s2[HID], g_q2[HID];     // reset by poolmlp last-block ticket
__device__ int   g_start[N_GRAPHS + 1];
__device__ int   g_ticket;                 // reset by the same last block

__device__ __forceinline__ unsigned long long ffma2(unsigned long long a,
                                                    unsigned long long b,
                                                    unsigned long long c) {
    unsigned long long d;
    asm("fma.rn.f32x2 %0, %1, %2, %3;" : "=l"(d) : "l"(a), "l"(b), "l"(c));
    return d;
}
__device__ __forceinline__ void redf(float* p, float v) {
    asm volatile("red.global.add.f32 [%0], %1;" :: "l"(p), "f"(v) : "memory");
}
__device__ __forceinline__ __half2 h2shfl_xor(__half2 v, int m) {
    unsigned u = *(unsigned*)&v;
    u = __shfl_xor_sync(0xffffffffu, u, m);
    return *(__half2*)&u;
}

// ---------------- degree (atomic w/ return -> edge rank) + graph-start boundaries ----
__global__ void deg_kernel(const int* __restrict__ ei, const int* __restrict__ batch) {
    int t = blockIdx.x * 256 + threadIdx.x;       // 524288 threads
    int4 d = __ldg((const int4*)(ei + N_EDGES) + t);
    int4 r;
    r.x = atomicAdd(&g_degi[d.x], 1);
    r.y = atomicAdd(&g_degi[d.y], 1);
    r.z = atomicAdd(&g_degi[d.z], 1);
    r.w = atomicAdd(&g_degi[d.w], 1);
    *((int4*)g_rank + t) = r;
    if (t < N_NODES) {
        int b = __ldg(batch + t);
        int prev = (t == 0) ? -1 : __ldg(batch + t - 1);
        for (int g = prev + 1; g <= b; g++) g_start[g] = t;
        if (t == N_NODES - 1)
            for (int g = b + 1; g <= N_GRAPHS; g++) g_start[g] = N_NODES;
    }
}

// ---------------- single-pass scan over PADDED degrees (+self edge) + dinv + y1 ------
__global__ __launch_bounds__(256) void scan_kernel(const float* __restrict__ x) {
    __shared__ int sh[256];
    __shared__ int s_off;
    int tid = threadIdx.x;
    int bid = blockIdx.x;
    int n = bid * 256 + tid;
    int d = g_degi[n];
    int dp = (d + 8) & ~7;          // self edge + pad to multiple of 8
    sh[tid] = dp;
    __syncthreads();
#pragma unroll
    for (int off = 1; off < 256; off <<= 1) {
        int v = (tid >= off) ? sh[tid - off] : 0;
        __syncthreads();
        sh[tid] += v;
        __syncthreads();
    }
    int total = sh[255];
    if (tid == 0) {
        if (bid == 0) {
            atomicExch(&g_scanstat[0], (2ull << 32) | (unsigned)total);
            s_off = 0;
        } else {
            atomicExch(&g_scanstat[bid], (1ull << 32) | (unsigned)total);
            long long running = 0;
            int p = bid - 1;
            while (p >= 0) {
                unsigned long long st;
                do { st = atomicAdd(&g_scanstat[p], 0ull); } while ((st >> 32) == 0ull);
                running += (unsigned)st;
                if ((st >> 32) == 2ull) break;
                p--;
            }
            atomicExch(&g_scanstat[bid], (2ull << 32) | (unsigned)(running + total));
            s_off = (int)running;
        }
    }
    __syncthreads();
    int rs = s_off + sh[tid] - dp;   // exclusive prefix (padded)
    g_rowstart[n] = rs;
    g_srt[rs + d] = n;                                     // self edge
    for (int p = d + 1; p < dp; p++) g_srt[rs + p] = N_NODES;  // dummy zero rows
    float dv = rsqrtf((float)d + 1.0f);
    g_dinv[n] = dv;
    const float4* xr = (const float4*)(x + (size_t)n * F_IN);
    uint4* yw = (uint4*)(g_y1 + (size_t)n * 16);
#pragma unroll
    for (int q = 0; q < 2; q++) {
        float4 v0 = __ldg(xr + 4 * q + 0);
        float4 v1 = __ldg(xr + 4 * q + 1);
        float4 v2 = __ldg(xr + 4 * q + 2);
        float4 v3 = __ldg(xr + 4 * q + 3);
        __half2 h0 = __floats2half2_rn(v0.x * dv, v0.y * dv);
        __half2 h1 = __floats2half2_rn(v0.z * dv, v0.w * dv);
        __half2 h2 = __floats2half2_rn(v1.x * dv, v1.y * dv);
        __half2 h3 = __floats2half2_rn(v1.z * dv, v1.w * dv);
        __half2 h4 = __floats2half2_rn(v2.x * dv, v2.y * dv);
        __half2 h5 = __floats2half2_rn(v2.z * dv, v2.w * dv);
        __half2 h6 = __floats2half2_rn(v3.x * dv, v3.y * dv);
        __half2 h7 = __floats2half2_rn(v3.z * dv, v3.w * dv);
        uint4 w0, w1;
        w0.x = *(unsigned*)&h0; w0.y = *(unsigned*)&h1;
        w0.z = *(unsigned*)&h2; w0.w = *(unsigned*)&h3;
        w1.x = *(unsigned*)&h4; w1.y = *(unsigned*)&h5;
        w1.z = *(unsigned*)&h6; w1.w = *(unsigned*)&h7;
        yw[2 * q + 0] = w0;
        yw[2 * q + 1] = w1;
    }
}

// ---------------- bucket edges by dst (no atomics: rowstart + precomputed rank) ------
__global__ void bucket_kernel(const int* __restrict__ ei) {
    int e4 = blockIdx.x * 256 + threadIdx.x;
    int4 s = __ldg((const int4*)ei + e4);
    int4 d = __ldg((const int4*)(ei + N_EDGES) + e4);
    int4 r = *((const int4*)g_rank + e4);
    g_srt[__ldg(&g_rowstart[d.x]) + r.x] = s.x;
    g_srt[__ldg(&g_rowstart[d.y]) + r.y] = s.y;
    g_srt[__ldg(&g_rowstart[d.z]) + r.z] = s.z;
    g_srt[__ldg(&g_rowstart[d.w]) + r.w] = s.w;
}

// ---------------- CSR aggregate, layer 1 (64B rows; 4 groups x 8 uint2 slices) ------
// Dual accumulator banks; next-rep rowstart/deg prefetched.
__global__ __launch_bounds__(256) void agg1_kernel() {
    int warp = blockIdx.x * 8 + (threadIdx.x >> 5);
    int lane = threadIdx.x & 31;
    int sl = lane & 7;          // uint2 slice (8 per 64B row)
    int grp = lane >> 3;        // 4 neighbor groups
    const uint2* yb = (const uint2*)g_y1;   // 8 uint2 per row
    int nb = warp * 8;
    int rs_n = __ldg(&g_rowstart[nb]);
    int dp_n = (__ldg(&g_degi[nb]) + 8) & ~7;
#pragma unroll 1
    for (int rep = 0; rep < 8; rep++) {
        int n = nb + rep;
        int rs = rs_n, degp = dp_n;
        if (rep < 7) {
            rs_n = __ldg(&g_rowstart[n + 1]);
            dp_n = (__ldg(&g_degi[n + 1]) + 8) & ~7;
        }
        __half2 zz = __float2half2_rn(0.f);
        __half2 a0 = zz, a1 = zz, b0 = zz, b1 = zz;
        for (int base = 0; base < degp; base += 32) {
            int cnt = min(32, degp - base);         // multiple of 8
            int idx = __ldg(&g_srt[rs + base + min(lane, cnt - 1)]);
#pragma unroll 4
            for (int p = 0; p < cnt; p += 8) {
                int j0 = __shfl_sync(0xffffffffu, idx, p + grp);
                int j1 = __shfl_sync(0xffffffffu, idx, p + 4 + grp);
                uint2 u0 = __ldg(yb + (size_t)j0 * 8 + sl);
                uint2 u1 = __ldg(yb + (size_t)j1 * 8 + sl);
                a0 = __hadd2(a0, *(__half2*)&u0.x);
                a1 = __hadd2(a1, *(__half2*)&u0.y);
                b0 = __hadd2(b0, *(__half2*)&u1.x);
                b1 = __hadd2(b1, *(__half2*)&u1.y);
            }
        }
        a0 = __hadd2(a0, b0);
        a1 = __hadd2(a1, b1);
#pragma unroll
        for (int m = 8; m <= 16; m <<= 1) {
            a0 = __hadd2(a0, h2shfl_xor(a0, m));
            a1 = __hadd2(a1, h2shfl_xor(a1, m));
        }
        if (grp == 0) {
            __half2 hd = __float2half2_rn(__ldg(&g_dinv[n]));
            a0 = __hmul2(a0, hd);
            a1 = __hmul2(a1, hd);
            uint2 o;
            o.x = *(unsigned*)&a0; o.y = *(unsigned*)&a1;
            *((uint2*)g_a1 + (size_t)n * 8 + sl) = o;
        }
    }
}

// ---------------- CSR aggregate, layer 2 (128B rows; 4 groups x 8 uint4 slices) -----
// Dual accumulator banks; prefetch; also resets g_s1/g_q1.
__global__ __launch_bounds__(256) void agg2_kernel() {
    if (blockIdx.x == 0 && threadIdx.x < HID) {
        g_s1[threadIdx.x] = 0.f;
        g_q1[threadIdx.x] = 0.f;
    }
    int warp = blockIdx.x * 8 + (threadIdx.x >> 5);
    int lane = threadIdx.x & 31;
    int sl = lane & 7;          // 16B slice (8 per 128B row)
    int grp = lane >> 3;        // 4 neighbor groups
    const uint4* yb = (const uint4*)g_y2;   // 8 uint4 per row
    int nb = warp * 8;
    int rs_n = __ldg(&g_rowstart[nb]);
    int dp_n = (__ldg(&g_degi[nb]) + 8) & ~7;
#pragma unroll 1
    for (int rep = 0; rep < 8; rep++) {
        int n = nb + rep;
        int rs = rs_n, degp = dp_n;
        if (rep < 7) {
            rs_n = __ldg(&g_rowstart[n + 1]);
            dp_n = (__ldg(&g_degi[n + 1]) + 8) & ~7;
        }
        __half2 zz = __float2half2_rn(0.f);
        __half2 a0 = zz, a1 = zz, a2 = zz, a3 = zz;
        __half2 b0 = zz, b1 = zz, b2 = zz, b3 = zz;
        for (int base = 0; base < degp; base += 32) {
            int cnt = min(32, degp - base);
            int idx = __ldg(&g_srt[rs + base + min(lane, cnt - 1)]);
#pragma unroll 4
            for (int p = 0; p < cnt; p += 8) {
                int j0 = __shfl_sync(0xffffffffu, idx, p + grp);
                int j1 = __shfl_sync(0xffffffffu, idx, p + 4 + grp);
                uint4 u0 = __ldg(yb + (size_t)j0 * 8 + sl);
                uint4 u1 = __ldg(yb + (size_t)j1 * 8 + sl);
                a0 = __hadd2(a0, *(__half2*)&u0.x);
                a1 = __hadd2(a1, *(__half2*)&u0.y);
                a2 = __hadd2(a2, *(__half2*)&u0.z);
                a3 = __hadd2(a3, *(__half2*)&u0.w);
                b0 = __hadd2(b0, *(__half2*)&u1.x);
                b1 = __hadd2(b1, *(__half2*)&u1.y);
                b2 = __hadd2(b2, *(__half2*)&u1.z);
                b3 = __hadd2(b3, *(__half2*)&u1.w);
            }
        }
        a0 = __hadd2(a0, b0);
        a1 = __hadd2(a1, b1);
        a2 = __hadd2(a2, b2);
        a3 = __hadd2(a3, b3);
#pragma unroll
        for (int m = 8; m <= 16; m <<= 1) {
            a0 = __hadd2(a0, h2shfl_xor(a0, m));
            a1 = __hadd2(a1, h2shfl_xor(a1, m));
            a2 = __hadd2(a2, h2shfl_xor(a2, m));
            a3 = __hadd2(a3, h2shfl_xor(a3, m));
        }
        if (grp == 0) {
            __half2 hd = __float2half2_rn(__ldg(&g_dinv[n]));
            a0 = __hmul2(a0, hd);
            a1 = __hmul2(a1, hd);
            a2 = __hmul2(a2, hd);
            a3 = __hmul2(a3, hd);
            uint4 o;
            o.x = *(unsigned*)&a0; o.y = *(unsigned*)&a1;
            o.z = *(unsigned*)&a2; o.w = *(unsigned*)&a3;
            *((uint4*)g_a2 + (size_t)n * 8 + sl) = o;
        }
    }
}

// ---------------- GEMM: z = a @ W + b ; fused BN stats ----------------
template <int K>
__global__ __launch_bounds__(128) void xw_kernel(const __half2* __restrict__ av,
                                                 __half2* __restrict__ zv,
                                                 const float* __restrict__ W,
                                                 const float* __restrict__ b,
                                                 float* __restrict__ sArr,
                                                 float* __restrict__ qArr) {
    __shared__ __align__(16) float sW[K * HID];
    __shared__ __half2 sOut[128][33];
    __shared__ float ps[4][64], pq[4][64];
    int tid = threadIdx.x;
    for (int i = tid; i < K * HID; i += 128) sW[i] = W[i];
    __syncthreads();
    int n = blockIdx.x * 128 + tid;
    float in[K];
    {
        const uint4* r = (const uint4*)(av + (size_t)n * (K / 2));
#pragma unroll
        for (int q = 0; q < K / 8; q++) {
            uint4 u = __ldg(r + q);
            unsigned uu[4] = {u.x, u.y, u.z, u.w};
#pragma unroll
            for (int m = 0; m < 4; m++) {
                float2 f = __half22float2(*(__half2*)&uu[m]);
                in[8 * q + 2 * m + 0] = f.x;
                in[8 * q + 2 * m + 1] = f.y;
            }
        }
    }
#pragma unroll 1
    for (int jb = 0; jb < 4; jb++) {
        unsigned long long acc[8];
#pragma unroll
        for (int m = 0; m < 8; m++) acc[m] = 0ull;
#pragma unroll 4
        for (int k = 0; k < K; k++) {
            unsigned long long xp;
            asm("mov.b64 %0, {%1, %1};" : "=l"(xp) : "r"(__float_as_uint(in[k])));
            const ulonglong2* wp = (const ulonglong2*)(sW + k * HID + jb * 16);
            ulonglong2 w01 = wp[0], w23 = wp[1], w45 = wp[2], w67 = wp[3];
            acc[0] = ffma2(xp, w01.x, acc[0]);
            acc[1] = ffma2(xp, w01.y, acc[1]);
            acc[2] = ffma2(xp, w23.x, acc[2]);
            acc[3] = ffma2(xp, w23.y, acc[3]);
            acc[4] = ffma2(xp, w45.x, acc[4]);
            acc[5] = ffma2(xp, w45.y, acc[5]);
            acc[6] = ffma2(xp, w67.x, acc[6]);
            acc[7] = ffma2(xp, w67.y, acc[7]);
        }
#pragma unroll
        for (int m = 0; m < 8; m++) {
            float lo, hi;
            asm("mov.b64 {%0, %1}, %2;" : "=f"(lo), "=f"(hi) : "l"(acc[m]));
            int f0 = jb * 16 + 2 * m;
            sOut[tid][jb * 8 + m] = __floats2half2_rn(lo + __ldg(b + f0),
                                                      hi + __ldg(b + f0 + 1));
        }
    }
    __syncthreads();
    unsigned* dst = (unsigned*)(zv + (size_t)blockIdx.x * 128 * 32);
    const unsigned* srcBase = (const unsigned*)sOut;
#pragma unroll
    for (int i = tid; i < 4096; i += 128) {
        int node = i >> 5, c = i & 31;
        dst[i] = srcBase[node * 33 + c];
    }
    {
        int c = tid & 31, part = tid >> 5;
        float s0 = 0.f, s1 = 0.f, q0 = 0.f, q1 = 0.f;
#pragma unroll 4
        for (int m = 0; m < 32; m++) {
            float2 f = __half22float2(sOut[part * 32 + m][c]);
            s0 += f.x; s1 += f.y; q0 += f.x * f.x; q1 += f.y * f.y;
        }
        ps[part][2 * c] = s0; ps[part][2 * c + 1] = s1;
        pq[part][2 * c] = q0; pq[part][2 * c + 1] = q1;
    }
    __syncthreads();
    if (tid < 64) {
        float s = ps[0][tid] + ps[1][tid] + ps[2][tid] + ps[3][tid];
        float q = pq[0][tid] + pq[1][tid] + pq[2][tid] + pq[3][tid];
        redf(sArr + tid, s);
        redf(qArr + tid, q);
    }
}

// ---------------- prep2: y2 = fp16(dinv * relu(bn1(z1))) ----------------
__global__ __launch_bounds__(256) void prep2_kernel(const float* __restrict__ gamma,
                                                    const float* __restrict__ beta) {
    __shared__ float sc[HID], sh[HID];
    int tid = threadIdx.x;
    if (tid < HID) {
        const float inv_n = 1.0f / (float)N_NODES;
        float mu = g_s1[tid] * inv_n;
        float var = g_q1[tid] * inv_n - mu * mu;
        float rstd = rsqrtf(var + BN_EPS);
        float s = rstd * __ldg(gamma + tid);
        sc[tid] = s;
        sh[tid] = __ldg(beta + tid) - mu * s;
    }
    __syncthreads();
    int i4 = blockIdx.x * 256 + tid;
    int n = i4 >> 3;
    int fb = (i4 & 7) * 8;
    float d = __ldg(&g_dinv[n]);
    uint4 u = *((const uint4*)g_z1 + i4);
    unsigned uu[4] = {u.x, u.y, u.z, u.w};
    uint4 o;
    unsigned* oo = (unsigned*)&o;
#pragma unroll
    for (int m = 0; m < 4; m++) {
        float2 f = __half22float2(*(__half2*)&uu[m]);
        int f0 = fb + 2 * m;
        float y0 = fmaxf(f.x * sc[f0] + sh[f0], 0.f) * d;
        float y1 = fmaxf(f.y * sc[f0 + 1] + sh[f0 + 1], 0.f) * d;
        __half2 h = __floats2half2_rn(y0, y1);
        oo[m] = *(unsigned*)&h;
    }
    *((uint4*)g_y2 + i4) = o;
}

// ---------------- fused pool + MLP heads + state recycling ----------------
__global__ __launch_bounds__(256) void poolmlp_kernel(
    const float* __restrict__ gamma, const float* __restrict__ beta,
    const float* __restrict__ gf,
    const float* __restrict__ Wo1, const float* __restrict__ bo1,
    const float* __restrict__ Wo2, const float* __restrict__ bo2,
    const float* __restrict__ Wb1, const float* __restrict__ bb1,
    const float* __restrict__ Wb2, const float* __restrict__ bb2,
    float* __restrict__ out) {
    int g = (blockIdx.x * 256 + threadIdx.x) >> 5;
    int lane = threadIdx.x & 31;
    int s = g_start[g], e = g_start[g + 1];
    int c = e - s;
    const float inv_n = 1.0f / (float)N_NODES;
    int f0 = 2 * lane, f1 = 2 * lane + 1;
    float mu0 = g_s2[f0] * inv_n, mu1 = g_s2[f1] * inv_n;
    float v0 = g_q2[f0] * inv_n - mu0 * mu0;
    float v1 = g_q2[f1] * inv_n - mu1 * mu1;
    float sc0 = rsqrtf(v0 + BN_EPS) * __ldg(gamma + f0);
    float sc1 = rsqrtf(v1 + BN_EPS) * __ldg(gamma + f1);
    float sh0 = __ldg(beta + f0) - mu0 * sc0;
    float sh1 = __ldg(beta + f1) - mu1 * sc1;

    // recycle state not read by this kernel: g_degi, g_scanstat
    {
        int t = blockIdx.x * 256 + threadIdx.x;       // 32768 threads
        uint4 zz = make_uint4(0u, 0u, 0u, 0u);
        *((uint4*)g_degi + t) = zz;                    // 131072 ints = 32768 uint4
        if (t < 512) g_scanstat[t] = 0ull;
    }

    float s0 = 0.f, s1 = 0.f;
    int i = s;
    for (; i + 4 <= e; i += 4) {
        float2 a0 = __half22float2(g_z2[(size_t)(i + 0) * 32 + lane]);
        float2 a1 = __half22float2(g_z2[(size_t)(i + 1) * 32 + lane]);
        float2 a2 = __half22float2(g_z2[(size_t)(i + 2) * 32 + lane]);
        float2 a3 = __half22float2(g_z2[(size_t)(i + 3) * 32 + lane]);
        s0 += fmaxf(a0.x * sc0 + sh0, 0.f) + fmaxf(a1.x * sc0 + sh0, 0.f)
            + fmaxf(a2.x * sc0 + sh0, 0.f) + fmaxf(a3.x * sc0 + sh0, 0.f);
        s1 += fmaxf(a0.y * sc1 + sh1, 0.f) + fmaxf(a1.y * sc1 + sh1, 0.f)
            + fmaxf(a2.y * sc1 + sh1, 0.f) + fmaxf(a3.y * sc1 + sh1, 0.f);
    }
    for (; i < e; i++) {
        float2 f = __half22float2(g_z2[(size_t)i * 32 + lane]);
        s0 += fmaxf(f.x * sc0 + sh0, 0.f);
        s1 += fmaxf(f.y * sc1 + sh1, 0.f);
    }
    float inv = (c > 0) ? 1.0f / (float)c : 0.f;
    float p0 = s0 * inv, p1 = s1 * inv;

    // heads: hidden unit = lane (32 units)
    float hO = __ldg(bo1 + lane), hB = __ldg(bb1 + lane);
#pragma unroll 8
    for (int i2 = 0; i2 < 32; i2++) {
        float c0 = __shfl_sync(0xffffffffu, p0, i2);
        float c1 = __shfl_sync(0xffffffffu, p1, i2);
        hO += c0 * __ldg(Wo1 + (2 * i2) * 32 + lane) + c1 * __ldg(Wo1 + (2 * i2 + 1) * 32 + lane);
        hB += c0 * __ldg(Wb1 + (2 * i2) * 32 + lane) + c1 * __ldg(Wb1 + (2 * i2 + 1) * 32 + lane);
    }
#pragma unroll
    for (int i3 = 0; i3 < G_FEAT; i3++) {
        float ci = __ldg(gf + (size_t)g * G_FEAT + i3);
        hO += ci * __ldg(Wo1 + (HID + i3) * 32 + lane);
        hB += ci * __ldg(Wb1 + (HID + i3) * 32 + lane);
    }
    hO = fmaxf(hO, 0.f);
    hB = fmaxf(hB, 0.f);
    float vO = hO * __ldg(Wo2 + lane);
    float vB = hB * __ldg(Wb2 + lane);
#pragma unroll
    for (int off = 16; off; off >>= 1) {
        vO += __shfl_down_sync(0xffffffffu, vO, off);
        vB += __shfl_down_sync(0xffffffffu, vB, off);
    }
    if (lane == 0) {
        out[g] = vO + __ldg(bo2);
        out[N_GRAPHS + g] = vB + __ldg(bb2);
    }

    // last-block ticket resets g_s2/g_q2 after every block has read them
    __syncthreads();
    if (threadIdx.x == 0) {
        int old = atomicAdd(&g_ticket, 1);
        if (old == (int)gridDim.x - 1) {
            for (int f = 0; f < HID; f++) { g_s2[f] = 0.f; g_q2[f] = 0.f; }
            g_ticket = 0;
        }
    }
}

// ---------------- launch ----------------
extern "C" void kernel_launch(void* const* d_in, const int* in_sizes, int n_in,
                              void* d_out, int out_size) {
    const float* x      = (const float*)d_in[0];
    const int*   ei     = (const int*)  d_in[1];
    const int*   batch  = (const int*)  d_in[2];
    const float* gfeat  = (const float*)d_in[3];
    const float* W1     = (const float*)d_in[4];
    const float* b1     = (const float*)d_in[5];
    const float* gamma1 = (const float*)d_in[6];
    const float* beta1  = (const float*)d_in[7];
    const float* W2     = (const float*)d_in[8];
    const float* b2     = (const float*)d_in[9];
    const float* gamma2 = (const float*)d_in[10];
    const float* beta2  = (const float*)d_in[11];
    const float* Wo1    = (const float*)d_in[12];
    const float* bo1    = (const float*)d_in[13];
    const float* Wo2    = (const float*)d_in[14];
    const float* bo2    = (const float*)d_in[15];
    const float* Wb1    = (const float*)d_in[16];
    const float* bb1    = (const float*)d_in[17];
    const float* Wb2    = (const float*)d_in[18];
    const float* bb2    = (const float*)d_in[19];
    float* out = (float*)d_out;

    float* s1; float* q1; float* s2; float* q2;
    cudaGetSymbolAddress((void**)&s1, g_s1);
    cudaGetSymbolAddress((void**)&q1, g_q1);
    cudaGetSymbolAddress((void**)&s2, g_s2);
    cudaGetSymbolAddress((void**)&q2, g_q2);
    __half2* a1; __half2* z1; __half2* a2; __half2* z2;
    cudaGetSymbolAddress((void**)&a1, g_a1);
    cudaGetSymbolAddress((void**)&z1, g_z1);
    cudaGetSymbolAddress((void**)&a2, g_a2);
    cudaGetSymbolAddress((void**)&z2, g_z2);

    deg_kernel<<<2048, 256>>>(ei, batch);       // 0
    scan_kernel<<<512, 256>>>(x);               // 1
    bucket_kernel<<<2048, 256>>>(ei);           // 2
    agg1_kernel<<<2048, 256>>>();               // 3  <- ncu capture slot
    xw_kernel<F_IN><<<N_NODES / 128, 128>>>(a1, z1, W1, b1, s1, q1);   // 4
    prep2_kernel<<<4096, 256>>>(gamma1, beta1); // 5
    agg2_kernel<<<2048, 256>>>();               // 6
    xw_kernel<HID><<<N_NODES / 128, 128>>>(a2, z2, W2, b2, s2, q2);    // 7
    poolmlp_kernel<<<128, 256>>>(gamma2, beta2, gfeat, Wo1, bo1, Wo2, bo2,
                                 Wb1, bb1, Wb2, bb2, out);             // 8
}

// round 13
// speedup vs baseline: 1.0064x; 1.0064x over previous
#include <cuda_runtime.h>
#include <cuda_fp16.h>
#include <cstdint>

#define N_NODES  131072
#define N_EDGES  2097152
#define F_IN     32
#define HID      64
#define G_FEAT   16
#define N_GRAPHS 1024
#define BN_EPS   1e-5f
#define SRT_CAP  (N_EDGES + 8 * N_NODES + 64)   // +64 tail guard for clampless window loads

// ---------------- device scratch (zero-initialized at load; recycled each run) --------
__device__ int   g_degi[N_NODES];          // zeroed by poolmlp (end of each run)
__device__ int   g_rowstart[N_NODES];
__device__ int   g_fill[N_NODES];
__device__ int   g_srt[SRT_CAP];
__device__ unsigned long long g_scanstat[512];  // zeroed by poolmlp
__device__ float g_dinv[N_NODES];
// +1 dummy zero row at index N_NODES (never written; stays zero)
__device__ __align__(16) __half2 g_y1[(size_t)(N_NODES + 1) * 16];  // dinv*x (32 feats)
__device__ __align__(16) __half2 g_a1[(size_t)N_NODES * 16];        // dinv*agg(y1)
__device__ __align__(16) __half2 g_z1[(size_t)N_NODES * 32];        // a1@W1+b1
__device__ __align__(16) __half2 g_y2[(size_t)(N_NODES + 1) * 32];  // dinv*relu(bn(z1))
__device__ __align__(16) __half2 g_a2[(size_t)N_NODES * 32];        // dinv*agg(y2)
__device__ __align__(16) __half2 g_z2[(size_t)N_NODES * 32];        // a2@W2+b2
__device__ float g_s1[HID], g_q1[HID];     // reset by agg2 (after prep2 reads them)
__device__ float g_s2[HID], g_q2[HID];     // reset by poolmlp last-block ticket
__device__ int   g_start[N_GRAPHS + 1];
__device__ int   g_ticket;                 // reset by the same last block

__device__ __forceinline__ unsigned long long ffma2(unsigned long long a,
                                                    unsigned long long b,
                                                    unsigned long long c) {
    unsigned long long d;
    asm("fma.rn.f32x2 %0, %1, %2, %3;" : "=l"(d) : "l"(a), "l"(b), "l"(c));
    return d;
}
__device__ __forceinline__ void redf(float* p, float v) {
    asm volatile("red.global.add.f32 [%0], %1;" :: "l"(p), "f"(v) : "memory");
}
__device__ __forceinline__ __half2 h2shfl_xor(__half2 v, int m) {
    unsigned u = *(unsigned*)&v;
    u = __shfl_xor_sync(0xffffffffu, u, m);
    return *(__half2*)&u;
}

// ---------------- degree (REDG, no return) + graph-start boundaries ----------------
__global__ void deg_kernel(const int* __restrict__ ei, const int* __restrict__ batch) {
    int t = blockIdx.x * 256 + threadIdx.x;       // 524288 threads
    int4 d = __ldg((const int4*)(ei + N_EDGES) + t);
    unsigned one = 1u;
    asm volatile("red.global.add.u32 [%0], %1;" :: "l"((unsigned*)(g_degi + d.x)), "r"(one) : "memory");
    asm volatile("red.global.add.u32 [%0], %1;" :: "l"((unsigned*)(g_degi + d.y)), "r"(one) : "memory");
    asm volatile("red.global.add.u32 [%0], %1;" :: "l"((unsigned*)(g_degi + d.z)), "r"(one) : "memory");
    asm volatile("red.global.add.u32 [%0], %1;" :: "l"((unsigned*)(g_degi + d.w)), "r"(one) : "memory");
    if (t < N_NODES) {
        int b = __ldg(batch + t);
        int prev = (t == 0) ? -1 : __ldg(batch + t - 1);
        for (int g = prev + 1; g <= b; g++) g_start[g] = t;
        if (t == N_NODES - 1)
            for (int g = b + 1; g <= N_GRAPHS; g++) g_start[g] = N_NODES;
    }
}

// ---------------- single-pass scan over PADDED degrees (+self edge) + dinv + y1 ------
__global__ __launch_bounds__(256) void scan_kernel(const float* __restrict__ x) {
    __shared__ int sh[256];
    __shared__ int s_off;
    int tid = threadIdx.x;
    int bid = blockIdx.x;
    int n = bid * 256 + tid;
    int d = g_degi[n];
    int dp = (d + 8) & ~7;          // self edge + pad to multiple of 8
    sh[tid] = dp;
    __syncthreads();
#pragma unroll
    for (int off = 1; off < 256; off <<= 1) {
        int v = (tid >= off) ? sh[tid - off] : 0;
        __syncthreads();
        sh[tid] += v;
        __syncthreads();
    }
    int total = sh[255];
    if (tid == 0) {
        if (bid == 0) {
            atomicExch(&g_scanstat[0], (2ull << 32) | (unsigned)total);
            s_off = 0;
        } else {
            atomicExch(&g_scanstat[bid], (1ull << 32) | (unsigned)total);
            long long running = 0;
            int p = bid - 1;
            while (p >= 0) {
                unsigned long long st;
                do { st = atomicAdd(&g_scanstat[p], 0ull); } while ((st >> 32) == 0ull);
                running += (unsigned)st;
                if ((st >> 32) == 2ull) break;
                p--;
            }
            atomicExch(&g_scanstat[bid], (2ull << 32) | (unsigned)(running + total));
            s_off = (int)running;
        }
    }
    __syncthreads();
    int rs = s_off + sh[tid] - dp;   // exclusive prefix (padded)
    g_rowstart[n] = rs;
    g_fill[n] = rs;
    g_srt[rs + d] = n;                                     // self edge
    for (int p = d + 1; p < dp; p++) g_srt[rs + p] = N_NODES;  // dummy zero rows
    float dv = rsqrtf((float)d + 1.0f);
    g_dinv[n] = dv;
    const float4* xr = (const float4*)(x + (size_t)n * F_IN);
    uint4* yw = (uint4*)(g_y1 + (size_t)n * 16);
#pragma unroll
    for (int q = 0; q < 2; q++) {
        float4 v0 = __ldg(xr + 4 * q + 0);
        float4 v1 = __ldg(xr + 4 * q + 1);
        float4 v2 = __ldg(xr + 4 * q + 2);
        float4 v3 = __ldg(xr + 4 * q + 3);
        __half2 h0 = __floats2half2_rn(v0.x * dv, v0.y * dv);
        __half2 h1 = __floats2half2_rn(v0.z * dv, v0.w * dv);
        __half2 h2 = __floats2half2_rn(v1.x * dv, v1.y * dv);
        __half2 h3 = __floats2half2_rn(v1.z * dv, v1.w * dv);
        __half2 h4 = __floats2half2_rn(v2.x * dv, v2.y * dv);
        __half2 h5 = __floats2half2_rn(v2.z * dv, v2.w * dv);
        __half2 h6 = __floats2half2_rn(v3.x * dv, v3.y * dv);
        __half2 h7 = __floats2half2_rn(v3.z * dv, v3.w * dv);
        uint4 w0, w1;
        w0.x = *(unsigned*)&h0; w0.y = *(unsigned*)&h1;
        w0.z = *(unsigned*)&h2; w0.w = *(unsigned*)&h3;
        w1.x = *(unsigned*)&h4; w1.y = *(unsigned*)&h5;
        w1.z = *(unsigned*)&h6; w1.w = *(unsigned*)&h7;
        yw[2 * q + 0] = w0;
        yw[2 * q + 1] = w1;
    }
}

// ---------------- bucket edges by dst (vectorized atomic fill) ----------------
__global__ void bucket_kernel(const int* __restrict__ ei) {
    int e4 = blockIdx.x * 256 + threadIdx.x;
    int4 s = __ldg((const int4*)ei + e4);
    int4 d = __ldg((const int4*)(ei + N_EDGES) + e4);
    g_srt[atomicAdd(&g_fill[d.x], 1)] = s.x;
    g_srt[atomicAdd(&g_fill[d.y], 1)] = s.y;
    g_srt[atomicAdd(&g_fill[d.z], 1)] = s.z;
    g_srt[atomicAdd(&g_fill[d.w], 1)] = s.w;
}

// ---------------- CSR aggregate, layer 1 (64B rows; 4 groups x 8 uint2 slices) ------
__global__ __launch_bounds__(256) void agg1_kernel() {
    int warp = blockIdx.x * 8 + (threadIdx.x >> 5);
    int lane = threadIdx.x & 31;
    int sl = lane & 7;          // uint2 slice (8 per 64B row)
    int grp = lane >> 3;        // 4 neighbor groups
    const uint2* yb = (const uint2*)g_y1;   // 8 uint2 per row
#pragma unroll 1
    for (int rep = 0; rep < 8; rep++) {
        int n = warp * 8 + rep;
        int rs = __ldg(&g_rowstart[n]);
        int degp = (__ldg(&g_degi[n]) + 8) & ~7;   // includes self + pad
        __half2 zz = __float2half2_rn(0.f);
        __half2 a0 = zz, a1 = zz;
        for (int base = 0; base < degp; base += 32) {
            int cnt = min(32, degp - base);         // multiple of 8
            int idx = __ldg(&g_srt[rs + base + lane]);   // lanes >= cnt load junk, never selected
#pragma unroll 8
            for (int p = 0; p < cnt; p += 4) {
                int j = __shfl_sync(0xffffffffu, idx, p + grp);
                uint2 u = __ldg(yb + (size_t)j * 8 + sl);
                a0 = __hadd2(a0, *(__half2*)&u.x);
                a1 = __hadd2(a1, *(__half2*)&u.y);
            }
        }
#pragma unroll
        for (int m = 8; m <= 16; m <<= 1) {
            a0 = __hadd2(a0, h2shfl_xor(a0, m));
            a1 = __hadd2(a1, h2shfl_xor(a1, m));
        }
        if (grp == 0) {
            __half2 hd = __float2half2_rn(__ldg(&g_dinv[n]));
            a0 = __hmul2(a0, hd);
            a1 = __hmul2(a1, hd);
            uint2 o;
            o.x = *(unsigned*)&a0; o.y = *(unsigned*)&a1;
            *((uint2*)g_a1 + (size_t)n * 8 + sl) = o;
        }
    }
}

// ---------------- CSR aggregate, layer 2 (128B rows; 4 groups x 8 uint4 slices) -----
// Also resets g_s1/g_q1 (safe: their reader prep2 ran before this kernel).
__global__ __launch_bounds__(256) void agg2_kernel() {
    if (blockIdx.x == 0 && threadIdx.x < HID) {
        g_s1[threadIdx.x] = 0.f;
        g_q1[threadIdx.x] = 0.f;
    }
    int warp = blockIdx.x * 8 + (threadIdx.x >> 5);
    int lane = threadIdx.x & 31;
    int sl = lane & 7;          // 16B slice (8 per 128B row)
    int grp = lane >> 3;        // 4 neighbor groups
    const uint4* yb = (const uint4*)g_y2;   // 8 uint4 per row
#pragma unroll 1
    for (int rep = 0; rep < 8; rep++) {
        int n = warp * 8 + rep;
        int rs = __ldg(&g_rowstart[n]);
        int degp = (__ldg(&g_degi[n]) + 8) & ~7;   // includes self + pad
        __half2 zz = __float2half2_rn(0.f);
        __half2 a0 = zz, a1 = zz, a2 = zz, a3 = zz;
        for (int base = 0; base < degp; base += 32) {
            int cnt = min(32, degp - base);
            int idx = __ldg(&g_srt[rs + base + lane]);
#pragma unroll 8
            for (int p = 0; p < cnt; p += 4) {
                int j = __shfl_sync(0xffffffffu, idx, p + grp);
                uint4 u = __ldg(yb + (size_t)j * 8 + sl);
                a0 = __hadd2(a0, *(__half2*)&u.x);
                a1 = __hadd2(a1, *(__half2*)&u.y);
                a2 = __hadd2(a2, *(__half2*)&u.z);
                a3 = __hadd2(a3, *(__half2*)&u.w);
            }
        }
#pragma unroll
        for (int m = 8; m <= 16; m <<= 1) {
            a0 = __hadd2(a0, h2shfl_xor(a0, m));
            a1 = __hadd2(a1, h2shfl_xor(a1, m));
            a2 = __hadd2(a2, h2shfl_xor(a2, m));
            a3 = __hadd2(a3, h2shfl_xor(a3, m));
        }
        if (grp == 0) {
            __half2 hd = __float2half2_rn(__ldg(&g_dinv[n]));
            a0 = __hmul2(a0, hd);
            a1 = __hmul2(a1, hd);
            a2 = __hmul2(a2, hd);
            a3 = __hmul2(a3, hd);
            uint4 o;
            o.x = *(unsigned*)&a0; o.y = *(unsigned*)&a1;
            o.z = *(unsigned*)&a2; o.w = *(unsigned*)&a3;
            *((uint4*)g_a2 + (size_t)n * 8 + sl) = o;
        }
    }
}

// ---------------- GEMM: z = a @ W + b ; fused BN stats ----------------
template <int K>
__global__ __launch_bounds__(128) void xw_kernel(const __half2* __restrict__ av,
                                                 __half2* __restrict__ zv,
                                                 const float* __restrict__ W,
                                                 const float* __restrict__ b,
                                                 float* __restrict__ sArr,
                                                 float* __restrict__ qArr) {
    __shared__ __align__(16) float sW[K * HID];
    __shared__ __half2 sOut[128][33];
    __shared__ float ps[4][64], pq[4][64];
    int tid = threadIdx.x;
    for (int i = tid; i < K * HID; i += 128) sW[i] = W[i];
    __syncthreads();
    int n = blockIdx.x * 128 + tid;
    float in[K];
    {
        const uint4* r = (const uint4*)(av + (size_t)n * (K / 2));
#pragma unroll
        for (int q = 0; q < K / 8; q++) {
            uint4 u = __ldg(r + q);
            unsigned uu[4] = {u.x, u.y, u.z, u.w};
#pragma unroll
            for (int m = 0; m < 4; m++) {
                float2 f = __half22float2(*(__half2*)&uu[m]);
                in[8 * q + 2 * m + 0] = f.x;
                in[8 * q + 2 * m + 1] = f.y;
            }
        }
    }
#pragma unroll 1
    for (int jb = 0; jb < 4; jb++) {
        unsigned long long acc[8];
#pragma unroll
        for (int m = 0; m < 8; m++) acc[m] = 0ull;
#pragma unroll 4
        for (int k = 0; k < K; k++) {
            unsigned long long xp;
            asm("mov.b64 %0, {%1, %1};" : "=l"(xp) : "r"(__float_as_uint(in[k])));
            const ulonglong2* wp = (const ulonglong2*)(sW + k * HID + jb * 16);
            ulonglong2 w01 = wp[0], w23 = wp[1], w45 = wp[2], w67 = wp[3];
            acc[0] = ffma2(xp, w01.x, acc[0]);
            acc[1] = ffma2(xp, w01.y, acc[1]);
            acc[2] = ffma2(xp, w23.x, acc[2]);
            acc[3] = ffma2(xp, w23.y, acc[3]);
            acc[4] = ffma2(xp, w45.x, acc[4]);
            acc[5] = ffma2(xp, w45.y, acc[5]);
            acc[6] = ffma2(xp, w67.x, acc[6]);
            acc[7] = ffma2(xp, w67.y, acc[7]);
        }
#pragma unroll
        for (int m = 0; m < 8; m++) {
            float lo, hi;
            asm("mov.b64 {%0, %1}, %2;" : "=f"(lo), "=f"(hi) : "l"(acc[m]));
            int f0 = jb * 16 + 2 * m;
            sOut[tid][jb * 8 + m] = __floats2half2_rn(lo + __ldg(b + f0),
                                                      hi + __ldg(b + f0 + 1));
        }
    }
    __syncthreads();
    unsigned* dst = (unsigned*)(zv + (size_t)blockIdx.x * 128 * 32);
    const unsigned* srcBase = (const unsigned*)sOut;
#pragma unroll
    for (int i = tid; i < 4096; i += 128) {
        int node = i >> 5, c = i & 31;
        dst[i] = srcBase[node * 33 + c];
    }
    {
        int c = tid & 31, part = tid >> 5;
        float s0 = 0.f, s1 = 0.f, q0 = 0.f, q1 = 0.f;
#pragma unroll 4
        for (int m = 0; m < 32; m++) {
            float2 f = __half22float2(sOut[part * 32 + m][c]);
            s0 += f.x; s1 += f.y; q0 += f.x * f.x; q1 += f.y * f.y;
        }
        ps[part][2 * c] = s0; ps[part][2 * c + 1] = s1;
        pq[part][2 * c] = q0; pq[part][2 * c + 1] = q1;
    }
    __syncthreads();
    if (tid < 64) {
        float s = ps[0][tid] + ps[1][tid] + ps[2][tid] + ps[3][tid];
        float q = pq[0][tid] + pq[1][tid] + pq[2][tid] + pq[3][tid];
        redf(sArr + tid, s);
        redf(qArr + tid, q);
    }
}

// ---------------- prep2: y2 = fp16(dinv * relu(bn1(z1))) ----------------
__global__ __launch_bounds__(256) void prep2_kernel(const float* __restrict__ gamma,
                                                    const float* __restrict__ beta) {
    __shared__ float sc[HID], sh[HID];
    int tid = threadIdx.x;
    if (tid < HID) {
        const float inv_n = 1.0f / (float)N_NODES;
        float mu = g_s1[tid] * inv_n;
        float var = g_q1[tid] * inv_n - mu * mu;
        float rstd = rsqrtf(var + BN_EPS);
        float s = rstd * __ldg(gamma + tid);
        sc[tid] = s;
        sh[tid] = __ldg(beta + tid) - mu * s;
    }
    __syncthreads();
    int i4 = blockIdx.x * 256 + tid;
    int n = i4 >> 3;
    int fb = (i4 & 7) * 8;
    float d = __ldg(&g_dinv[n]);
    uint4 u = *((const uint4*)g_z1 + i4);
    unsigned uu[4] = {u.x, u.y, u.z, u.w};
    uint4 o;
    unsigned* oo = (unsigned*)&o;
#pragma unroll
    for (int m = 0; m < 4; m++) {
        float2 f = __half22float2(*(__half2*)&uu[m]);
        int f0 = fb + 2 * m;
        float y0 = fmaxf(f.x * sc[f0] + sh[f0], 0.f) * d;
        float y1 = fmaxf(f.y * sc[f0 + 1] + sh[f0 + 1], 0.f) * d;
        __half2 h = __floats2half2_rn(y0, y1);
        oo[m] = *(unsigned*)&h;
    }
    *((uint4*)g_y2 + i4) = o;
}

// ---------------- fused pool + MLP heads + state recycling ----------------
__global__ __launch_bounds__(256) void poolmlp_kernel(
    const float* __restrict__ gamma, const float* __restrict__ beta,
    const float* __restrict__ gf,
    const float* __restrict__ Wo1, const float* __restrict__ bo1,
    const float* __restrict__ Wo2, const float* __restrict__ bo2,
    const float* __restrict__ Wb1, const float* __restrict__ bb1,
    const float* __restrict__ Wb2, const float* __restrict__ bb2,
    float* __restrict__ out) {
    int g = (blockIdx.x * 256 + threadIdx.x) >> 5;
    int lane = threadIdx.x & 31;
    int s = g_start[g], e = g_start[g + 1];
    int c = e - s;
    const float inv_n = 1.0f / (float)N_NODES;
    int f0 = 2 * lane, f1 = 2 * lane + 1;
    float mu0 = g_s2[f0] * inv_n, mu1 = g_s2[f1] * inv_n;
    float v0 = g_q2[f0] * inv_n - mu0 * mu0;
    float v1 = g_q2[f1] * inv_n - mu1 * mu1;
    float sc0 = rsqrtf(v0 + BN_EPS) * __ldg(gamma + f0);
    float sc1 = rsqrtf(v1 + BN_EPS) * __ldg(gamma + f1);
    float sh0 = __ldg(beta + f0) - mu0 * sc0;
    float sh1 = __ldg(beta + f1) - mu1 * sc1;

    // recycle state not read by this kernel: g_degi, g_scanstat
    {
        int t = blockIdx.x * 256 + threadIdx.x;       // 32768 threads
        uint4 zz = make_uint4(0u, 0u, 0u, 0u);
        *((uint4*)g_degi + t) = zz;                    // 131072 ints = 32768 uint4
        if (t < 512) g_scanstat[t] = 0ull;
    }

    float s0 = 0.f, s1 = 0.f;
    int i = s;
    for (; i + 4 <= e; i += 4) {
        float2 a0 = __half22float2(g_z2[(size_t)(i + 0) * 32 + lane]);
        float2 a1 = __half22float2(g_z2[(size_t)(i + 1) * 32 + lane]);
        float2 a2 = __half22float2(g_z2[(size_t)(i + 2) * 32 + lane]);
        float2 a3 = __half22float2(g_z2[(size_t)(i + 3) * 32 + lane]);
        s0 += fmaxf(a0.x * sc0 + sh0, 0.f) + fmaxf(a1.x * sc0 + sh0, 0.f)
            + fmaxf(a2.x * sc0 + sh0, 0.f) + fmaxf(a3.x * sc0 + sh0, 0.f);
        s1 += fmaxf(a0.y * sc1 + sh1, 0.f) + fmaxf(a1.y * sc1 + sh1, 0.f)
            + fmaxf(a2.y * sc1 + sh1, 0.f) + fmaxf(a3.y * sc1 + sh1, 0.f);
    }
    for (; i < e; i++) {
        float2 f = __half22float2(g_z2[(size_t)i * 32 + lane]);
        s0 += fmaxf(f.x * sc0 + sh0, 0.f);
        s1 += fmaxf(f.y * sc1 + sh1, 0.f);
    }
    float inv = (c > 0) ? 1.0f / (float)c : 0.f;
    float p0 = s0 * inv, p1 = s1 * inv;

    // heads: hidden unit = lane (32 units)
    float hO = __ldg(bo1 + lane), hB = __ldg(bb1 + lane);
#pragma unroll 8
    for (int i2 = 0; i2 < 32; i2++) {
        float c0 = __shfl_sync(0xffffffffu, p0, i2);
        float c1 = __shfl_sync(0xffffffffu, p1, i2);
        hO += c0 * __ldg(Wo1 + (2 * i2) * 32 + lane) + c1 * __ldg(Wo1 + (2 * i2 + 1) * 32 + lane);
        hB += c0 * __ldg(Wb1 + (2 * i2) * 32 + lane) + c1 * __ldg(Wb1 + (2 * i2 + 1) * 32 + lane);
    }
#pragma unroll
    for (int i3 = 0; i3 < G_FEAT; i3++) {
        float ci = __ldg(gf + (size_t)g * G_FEAT + i3);
        hO += ci * __ldg(Wo1 + (HID + i3) * 32 + lane);
        hB += ci * __ldg(Wb1 + (HID + i3) * 32 + lane);
    }
    hO = fmaxf(hO, 0.f);
    hB = fmaxf(hB, 0.f);
    float vO = hO * __ldg(Wo2 + lane);
    float vB = hB * __ldg(Wb2 + lane);
#pragma unroll
    for (int off = 16; off; off >>= 1) {
        vO += __shfl_down_sync(0xffffffffu, vO, off);
        vB += __shfl_down_sync(0xffffffffu, vB, off);
    }
    if (lane == 0) {
        out[g] = vO + __ldg(bo2);
        out[N_GRAPHS + g] = vB + __ldg(bb2);
    }

    // last-block ticket resets g_s2/g_q2 after every block has read them
    __syncthreads();
    if (threadIdx.x == 0) {
        int old = atomicAdd(&g_ticket, 1);
        if (old == (int)gridDim.x - 1) {
            for (int f = 0; f < HID; f++) { g_s2[f] = 0.f; g_q2[f] = 0.f; }
            g_ticket = 0;
        }
    }
}

// ---------------- launch ----------------
extern "C" void kernel_launch(void* const* d_in, const int* in_sizes, int n_in,
                              void* d_out, int out_size) {
    const float* x      = (const float*)d_in[0];
    const int*   ei     = (const int*)  d_in[1];
    const int*   batch  = (const int*)  d_in[2];
    const float* gfeat  = (const float*)d_in[3];
    const float* W1     = (const float*)d_in[4];
    const float* b1     = (const float*)d_in[5];
    const float* gamma1 = (const float*)d_in[6];
    const float* beta1  = (const float*)d_in[7];
    const float* W2     = (const float*)d_in[8];
    const float* b2     = (const float*)d_in[9];
    const float* gamma2 = (const float*)d_in[10];
    const float* beta2  = (const float*)d_in[11];
    const float* Wo1    = (const float*)d_in[12];
    const float* bo1    = (const float*)d_in[13];
    const float* Wo2    = (const float*)d_in[14];
    const float* bo2    = (const float*)d_in[15];
    const float* Wb1    = (const float*)d_in[16];
    const float* bb1    = (const float*)d_in[17];
    const float* Wb2    = (const float*)d_in[18];
    const float* bb2    = (const float*)d_in[19];
    float* out = (float*)d_out;

    float* s1; float* q1; float* s2; float* q2;
    cudaGetSymbolAddress((void**)&s1, g_s1);
    cudaGetSymbolAddress((void**)&q1, g_q1);
    cudaGetSymbolAddress((void**)&s2, g_s2);
    cudaGetSymbolAddress((void**)&q2, g_q2);
    __half2* a1; __half2* z1; __half2* a2; __half2* z2;
    cudaGetSymbolAddress((void**)&a1, g_a1);
    cudaGetSymbolAddress((void**)&z1, g_z1);
    cudaGetSymbolAddress((void**)&a2, g_a2);
    cudaGetSymbolAddress((void**)&z2, g_z2);

    deg_kernel<<<2048, 256>>>(ei, batch);       // 0
    scan_kernel<<<512, 256>>>(x);               // 1
    bucket_kernel<<<2048, 256>>>(ei);           // 2
    agg1_kernel<<<2048, 256>>>();               // 3  <- ncu capture slot
    xw_kernel<F_IN><<<N_NODES / 128, 128>>>(a1, z1, W1, b1, s1, q1);   // 4
    prep2_kernel<<<4096, 256>>>(gamma1, beta1); // 5
    agg2_kernel<<<2048, 256>>>();               // 6
    xw_kernel<HID><<<N_NODES / 128, 128>>>(a2, z2, W2, b2, s2, q2);    // 7
    poolmlp_kernel<<<128, 256>>>(gamma2, beta2, gfeat, Wo1, bo1, Wo2, bo2,
                                 Wb1, bb1, Wb2, bb2, out);             // 8
}

// round 14
// speedup vs baseline: 1.0074x; 1.0009x over previous
#include <cuda_runtime.h>
#include <cuda_fp16.h>
#include <cstdint>

#define N_NODES  131072
#define N_EDGES  2097152
#define F_IN     32
#define HID      64
#define G_FEAT   16
#define N_GRAPHS 1024
#define BN_EPS   1e-5f
#define SRT_CAP  (N_EDGES + 8 * N_NODES)

// ---------------- device scratch (zero-initialized at load; recycled each run) --------
__device__ int   g_degi[N_NODES];          // zeroed by poolmlp (end of each run)
__device__ int   g_rowstart[N_NODES];
__device__ int   g_fill[N_NODES];
__device__ int   g_srt[SRT_CAP];
__device__ unsigned long long g_scanstat[512];  // zeroed by poolmlp
__device__ float g_dinv[N_NODES];
// +1 dummy zero row at index N_NODES (never written; stays zero)
__device__ __align__(16) __half2 g_y1[(size_t)(N_NODES + 1) * 16];  // dinv*x (32 feats)
__device__ __align__(16) __half2 g_a1[(size_t)N_NODES * 16];        // dinv*agg(y1)
__device__ __align__(16) __half2 g_z1[(size_t)N_NODES * 32];        // a1@W1+b1
__device__ __align__(16) __half2 g_y2[(size_t)(N_NODES + 1) * 32];  // dinv*relu(bn(z1))
__device__ __align__(16) __half2 g_a2[(size_t)N_NODES * 32];        // dinv*agg(y2)
__device__ __align__(16) __half2 g_z2[(size_t)N_NODES * 32];        // a2@W2+b2
__device__ float g_s1[HID], g_q1[HID];     // reset by agg2 (after prep2 reads them)
__device__ float g_s2[HID], g_q2[HID];     // reset by poolmlp last-block ticket
__device__ int   g_start[N_GRAPHS + 1];
__device__ int   g_ticket;                 // reset by the same last block

__device__ __forceinline__ unsigned long long ffma2(unsigned long long a,
                                                    unsigned long long b,
                                                    unsigned long long c) {
    unsigned long long d;
    asm("fma.rn.f32x2 %0, %1, %2, %3;" : "=l"(d) : "l"(a), "l"(b), "l"(c));
    return d;
}
__device__ __forceinline__ void redf(float* p, float v) {
    asm volatile("red.global.add.f32 [%0], %1;" :: "l"(p), "f"(v) : "memory");
}
__device__ __forceinline__ __half2 h2shfl_xor(__half2 v, int m) {
    unsigned u = *(unsigned*)&v;
    u = __shfl_xor_sync(0xffffffffu, u, m);
    return *(__half2*)&u;
}

// ---------------- degree (REDG, no return) + graph-start boundaries ----------------
__global__ void deg_kernel(const int* __restrict__ ei, const int* __restrict__ batch) {
    int t = blockIdx.x * 256 + threadIdx.x;       // 524288 threads
    int4 d = __ldg((const int4*)(ei + N_EDGES) + t);
    unsigned one = 1u;
    asm volatile("red.global.add.u32 [%0], %1;" :: "l"((unsigned*)(g_degi + d.x)), "r"(one) : "memory");
    asm volatile("red.global.add.u32 [%0], %1;" :: "l"((unsigned*)(g_degi + d.y)), "r"(one) : "memory");
    asm volatile("red.global.add.u32 [%0], %1;" :: "l"((unsigned*)(g_degi + d.z)), "r"(one) : "memory");
    asm volatile("red.global.add.u32 [%0], %1;" :: "l"((unsigned*)(g_degi + d.w)), "r"(one) : "memory");
    if (t < N_NODES) {
        int b = __ldg(batch + t);
        int prev = (t == 0) ? -1 : __ldg(batch + t - 1);
        for (int g = prev + 1; g <= b; g++) g_start[g] = t;
        if (t == N_NODES - 1)
            for (int g = b + 1; g <= N_GRAPHS; g++) g_start[g] = N_NODES;
    }
}

// ---------------- single-pass scan over PADDED degrees (+self edge) + dinv + y1 ------
__global__ __launch_bounds__(256) void scan_kernel(const float* __restrict__ x) {
    __shared__ int sh[256];
    __shared__ int s_off;
    int tid = threadIdx.x;
    int bid = blockIdx.x;
    int n = bid * 256 + tid;
    int d = g_degi[n];
    int dp = (d + 8) & ~7;          // self edge + pad to multiple of 8
    sh[tid] = dp;
    __syncthreads();
#pragma unroll
    for (int off = 1; off < 256; off <<= 1) {
        int v = (tid >= off) ? sh[tid - off] : 0;
        __syncthreads();
        sh[tid] += v;
        __syncthreads();
    }
    int total = sh[255];
    if (tid == 0) {
        if (bid == 0) {
            atomicExch(&g_scanstat[0], (2ull << 32) | (unsigned)total);
            s_off = 0;
        } else {
            atomicExch(&g_scanstat[bid], (1ull << 32) | (unsigned)total);
            long long running = 0;
            int p = bid - 1;
            while (p >= 0) {
                unsigned long long st;
                do { st = atomicAdd(&g_scanstat[p], 0ull); } while ((st >> 32) == 0ull);
                running += (unsigned)st;
                if ((st >> 32) == 2ull) break;
                p--;
            }
            atomicExch(&g_scanstat[bid], (2ull << 32) | (unsigned)(running + total));
            s_off = (int)running;
        }
    }
    __syncthreads();
    int rs = s_off + sh[tid] - dp;   // exclusive prefix (padded)
    g_rowstart[n] = rs;
    g_fill[n] = rs;
    g_srt[rs + d] = n;                                     // self edge
    for (int p = d + 1; p < dp; p++) g_srt[rs + p] = N_NODES;  // dummy zero rows
    float dv = rsqrtf((float)d + 1.0f);
    g_dinv[n] = dv;
    const float4* xr = (const float4*)(x + (size_t)n * F_IN);
    uint4* yw = (uint4*)(g_y1 + (size_t)n * 16);
#pragma unroll
    for (int q = 0; q < 2; q++) {
        float4 v0 = __ldg(xr + 4 * q + 0);
        float4 v1 = __ldg(xr + 4 * q + 1);
        float4 v2 = __ldg(xr + 4 * q + 2);
        float4 v3 = __ldg(xr + 4 * q + 3);
        __half2 h0 = __floats2half2_rn(v0.x * dv, v0.y * dv);
        __half2 h1 = __floats2half2_rn(v0.z * dv, v0.w * dv);
        __half2 h2 = __floats2half2_rn(v1.x * dv, v1.y * dv);
        __half2 h3 = __floats2half2_rn(v1.z * dv, v1.w * dv);
        __half2 h4 = __floats2half2_rn(v2.x * dv, v2.y * dv);
        __half2 h5 = __floats2half2_rn(v2.z * dv, v2.w * dv);
        __half2 h6 = __floats2half2_rn(v3.x * dv, v3.y * dv);
        __half2 h7 = __floats2half2_rn(v3.z * dv, v3.w * dv);
        uint4 w0, w1;
        w0.x = *(unsigned*)&h0; w0.y = *(unsigned*)&h1;
        w0.z = *(unsigned*)&h2; w0.w = *(unsigned*)&h3;
        w1.x = *(unsigned*)&h4; w1.y = *(unsigned*)&h5;
        w1.z = *(unsigned*)&h6; w1.w = *(unsigned*)&h7;
        yw[2 * q + 0] = w0;
        yw[2 * q + 1] = w1;
    }
}

// ---------------- bucket edges by dst (vectorized atomic fill) ----------------
__global__ void bucket_kernel(const int* __restrict__ ei) {
    int e4 = blockIdx.x * 256 + threadIdx.x;
    int4 s = __ldg((const int4*)ei + e4);
    int4 d = __ldg((const int4*)(ei + N_EDGES) + e4);
    g_srt[atomicAdd(&g_fill[d.x], 1)] = s.x;
    g_srt[atomicAdd(&g_fill[d.y], 1)] = s.y;
    g_srt[atomicAdd(&g_fill[d.z], 1)] = s.z;
    g_srt[atomicAdd(&g_fill[d.w], 1)] = s.w;
}

// ---------------- CSR aggregate, layer 1 (64B rows; 4 groups x 8 uint2 slices) ------
__global__ __launch_bounds__(256) void agg1_kernel() {
    int warp = blockIdx.x * 8 + (threadIdx.x >> 5);
    int lane = threadIdx.x & 31;
    int sl = lane & 7;          // uint2 slice (8 per 64B row)
    int grp = lane >> 3;        // 4 neighbor groups
    const uint2* yb = (const uint2*)g_y1;   // 8 uint2 per row
#pragma unroll 1
    for (int rep = 0; rep < 8; rep++) {
        int n = warp * 8 + rep;
        int rs = __ldg(&g_rowstart[n]);
        int degp = (__ldg(&g_degi[n]) + 8) & ~7;   // includes self + pad
        __half2 zz = __float2half2_rn(0.f);
        __half2 a0 = zz, a1 = zz;
        for (int base = 0; base < degp; base += 32) {
            int cnt = min(32, degp - base);         // multiple of 8
            int idx = __ldg(&g_srt[rs + base + min(lane, cnt - 1)]);
#pragma unroll 8
            for (int p = 0; p < cnt; p += 4) {
                int j = __shfl_sync(0xffffffffu, idx, p + grp);
                uint2 u = __ldg(yb + (size_t)j * 8 + sl);
                a0 = __hadd2(a0, *(__half2*)&u.x);
                a1 = __hadd2(a1, *(__half2*)&u.y);
            }
        }
#pragma unroll
        for (int m = 8; m <= 16; m <<= 1) {
            a0 = __hadd2(a0, h2shfl_xor(a0, m));
            a1 = __hadd2(a1, h2shfl_xor(a1, m));
        }
        if (grp == 0) {
            __half2 hd = __float2half2_rn(__ldg(&g_dinv[n]));
            a0 = __hmul2(a0, hd);
            a1 = __hmul2(a1, hd);
            uint2 o;
            o.x = *(unsigned*)&a0; o.y = *(unsigned*)&a1;
            *((uint2*)g_a1 + (size_t)n * 8 + sl) = o;
        }
    }
}

// ---------------- CSR aggregate, layer 2 (128B rows; 4 groups x 8 uint4 slices) -----
// Also resets g_s1/g_q1 (safe: their reader prep2 ran before this kernel).
__global__ __launch_bounds__(256) void agg2_kernel() {
    if (blockIdx.x == 0 && threadIdx.x < HID) {
        g_s1[threadIdx.x] = 0.f;
        g_q1[threadIdx.x] = 0.f;
    }
    int warp = blockIdx.x * 8 + (threadIdx.x >> 5);
    int lane = threadIdx.x & 31;
    int sl = lane & 7;          // 16B slice (8 per 128B row)
    int grp = lane >> 3;        // 4 neighbor groups
    const uint4* yb = (const uint4*)g_y2;   // 8 uint4 per row
#pragma unroll 1
    for (int rep = 0; rep < 8; rep++) {
        int n = warp * 8 + rep;
        int rs = __ldg(&g_rowstart[n]);
        int degp = (__ldg(&g_degi[n]) + 8) & ~7;   // includes self + pad
        __half2 zz = __float2half2_rn(0.f);
        __half2 a0 = zz, a1 = zz, a2 = zz, a3 = zz;
        for (int base = 0; base < degp; base += 32) {
            int cnt = min(32, degp - base);
            int idx = __ldg(&g_srt[rs + base + min(lane, cnt - 1)]);
#pragma unroll 8
            for (int p = 0; p < cnt; p += 4) {
                int j = __shfl_sync(0xffffffffu, idx, p + grp);
                uint4 u = __ldg(yb + (size_t)j * 8 + sl);
                a0 = __hadd2(a0, *(__half2*)&u.x);
                a1 = __hadd2(a1, *(__half2*)&u.y);
                a2 = __hadd2(a2, *(__half2*)&u.z);
                a3 = __hadd2(a3, *(__half2*)&u.w);
            }
        }
#pragma unroll
        for (int m = 8; m <= 16; m <<= 1) {
            a0 = __hadd2(a0, h2shfl_xor(a0, m));
            a1 = __hadd2(a1, h2shfl_xor(a1, m));
            a2 = __hadd2(a2, h2shfl_xor(a2, m));
            a3 = __hadd2(a3, h2shfl_xor(a3, m));
        }
        if (grp == 0) {
            __half2 hd = __float2half2_rn(__ldg(&g_dinv[n]));
            a0 = __hmul2(a0, hd);
            a1 = __hmul2(a1, hd);
            a2 = __hmul2(a2, hd);
            a3 = __hmul2(a3, hd);
            uint4 o;
            o.x = *(unsigned*)&a0; o.y = *(unsigned*)&a1;
            o.z = *(unsigned*)&a2; o.w = *(unsigned*)&a3;
            *((uint4*)g_a2 + (size_t)n * 8 + sl) = o;
        }
    }
}

// ---------------- GEMM: z = a @ W + b ; fused BN stats ----------------
template <int K>
__global__ __launch_bounds__(128) void xw_kernel(const __half2* __restrict__ av,
                                                 __half2* __restrict__ zv,
                                                 const float* __restrict__ W,
                                                 const float* __restrict__ b,
                                                 float* __restrict__ sArr,
                                                 float* __restrict__ qArr) {
    __shared__ __align__(16) float sW[K * HID];
    __shared__ __half2 sOut[128][33];
    __shared__ float ps[4][64], pq[4][64];
    int tid = threadIdx.x;
    for (int i = tid; i < K * HID; i += 128) sW[i] = W[i];
    __syncthreads();
    int n = blockIdx.x * 128 + tid;
    float in[K];
    {
        const uint4* r = (const uint4*)(av + (size_t)n * (K / 2));
#pragma unroll
        for (int q = 0; q < K / 8; q++) {
            uint4 u = __ldg(r + q);
            unsigned uu[4] = {u.x, u.y, u.z, u.w};
#pragma unroll
            for (int m = 0; m < 4; m++) {
                float2 f = __half22float2(*(__half2*)&uu[m]);
                in[8 * q + 2 * m + 0] = f.x;
                in[8 * q + 2 * m + 1] = f.y;
            }
        }
    }
#pragma unroll 1
    for (int jb = 0; jb < 4; jb++) {
        unsigned long long acc[8];
#pragma unroll
        for (int m = 0; m < 8; m++) acc[m] = 0ull;
#pragma unroll 4
        for (int k = 0; k < K; k++) {
            unsigned long long xp;
            asm("mov.b64 %0, {%1, %1};" : "=l"(xp) : "r"(__float_as_uint(in[k])));
            const ulonglong2* wp = (const ulonglong2*)(sW + k * HID + jb * 16);
            ulonglong2 w01 = wp[0], w23 = wp[1], w45 = wp[2], w67 = wp[3];
            acc[0] = ffma2(xp, w01.x, acc[0]);
            acc[1] = ffma2(xp, w01.y, acc[1]);
            acc[2] = ffma2(xp, w23.x, acc[2]);
            acc[3] = ffma2(xp, w23.y, acc[3]);
            acc[4] = ffma2(xp, w45.x, acc[4]);
            acc[5] = ffma2(xp, w45.y, acc[5]);
            acc[6] = ffma2(xp, w67.x, acc[6]);
            acc[7] = ffma2(xp, w67.y, acc[7]);
        }
#pragma unroll
        for (int m = 0; m < 8; m++) {
            float lo, hi;
            asm("mov.b64 {%0, %1}, %2;" : "=f"(lo), "=f"(hi) : "l"(acc[m]));
            int f0 = jb * 16 + 2 * m;
            sOut[tid][jb * 8 + m] = __floats2half2_rn(lo + __ldg(b + f0),
                                                      hi + __ldg(b + f0 + 1));
        }
    }
    __syncthreads();
    unsigned* dst = (unsigned*)(zv + (size_t)blockIdx.x * 128 * 32);
    const unsigned* srcBase = (const unsigned*)sOut;
#pragma unroll
    for (int i = tid; i < 4096; i += 128) {
        int node = i >> 5, c = i & 31;
        dst[i] = srcBase[node * 33 + c];
    }
    {
        int c = tid & 31, part = tid >> 5;
        float s0 = 0.f, s1 = 0.f, q0 = 0.f, q1 = 0.f;
#pragma unroll 4
        for (int m = 0; m < 32; m++) {
            float2 f = __half22float2(sOut[part * 32 + m][c]);
            s0 += f.x; s1 += f.y; q0 += f.x * f.x; q1 += f.y * f.y;
        }
        ps[part][2 * c] = s0; ps[part][2 * c + 1] = s1;
        pq[part][2 * c] = q0; pq[part][2 * c + 1] = q1;
    }
    __syncthreads();
    if (tid < 64) {
        float s = ps[0][tid] + ps[1][tid] + ps[2][tid] + ps[3][tid];
        float q = pq[0][tid] + pq[1][tid] + pq[2][tid] + pq[3][tid];
        redf(sArr + tid, s);
        redf(qArr + tid, q);
    }
}

// ---------------- prep2: y2 = fp16(dinv * relu(bn1(z1))) ----------------
__global__ __launch_bounds__(256) void prep2_kernel(const float* __restrict__ gamma,
                                                    const float* __restrict__ beta) {
    __shared__ float sc[HID], sh[HID];
    int tid = threadIdx.x;
    if (tid < HID) {
        const float inv_n = 1.0f / (float)N_NODES;
        float mu = g_s1[tid] * inv_n;
        float var = g_q1[tid] * inv_n - mu * mu;
        float rstd = rsqrtf(var + BN_EPS);
        float s = rstd * __ldg(gamma + tid);
        sc[tid] = s;
        sh[tid] = __ldg(beta + tid) - mu * s;
    }
    __syncthreads();
    int i4 = blockIdx.x * 256 + tid;
    int n = i4 >> 3;
    int fb = (i4 & 7) * 8;
    float d = __ldg(&g_dinv[n]);
    uint4 u = *((const uint4*)g_z1 + i4);
    unsigned uu[4] = {u.x, u.y, u.z, u.w};
    uint4 o;
    unsigned* oo = (unsigned*)&o;
#pragma unroll
    for (int m = 0; m < 4; m++) {
        float2 f = __half22float2(*(__half2*)&uu[m]);
        int f0 = fb + 2 * m;
        float y0 = fmaxf(f.x * sc[f0] + sh[f0], 0.f) * d;
        float y1 = fmaxf(f.y * sc[f0 + 1] + sh[f0 + 1], 0.f) * d;
        __half2 h = __floats2half2_rn(y0, y1);
        oo[m] = *(unsigned*)&h;
    }
    *((uint4*)g_y2 + i4) = o;
}

// ---------------- fused pool + MLP heads + state recycling ----------------
__global__ __launch_bounds__(256) void poolmlp_kernel(
    const float* __restrict__ gamma, const float* __restrict__ beta,
    const float* __restrict__ gf,
    const float* __restrict__ Wo1, const float* __restrict__ bo1,
    const float* __restrict__ Wo2, const float* __restrict__ bo2,
    const float* __restrict__ Wb1, const float* __restrict__ bb1,
    const float* __restrict__ Wb2, const float* __restrict__ bb2,
    float* __restrict__ out) {
    int g = (blockIdx.x * 256 + threadIdx.x) >> 5;
    int lane = threadIdx.x & 31;
    int s = g_start[g], e = g_start[g + 1];
    int c = e - s;
    const float inv_n = 1.0f / (float)N_NODES;
    int f0 = 2 * lane, f1 = 2 * lane + 1;
    float mu0 = g_s2[f0] * inv_n, mu1 = g_s2[f1] * inv_n;
    float v0 = g_q2[f0] * inv_n - mu0 * mu0;
    float v1 = g_q2[f1] * inv_n - mu1 * mu1;
    float sc0 = rsqrtf(v0 + BN_EPS) * __ldg(gamma + f0);
    float sc1 = rsqrtf(v1 + BN_EPS) * __ldg(gamma + f1);
    float sh0 = __ldg(beta + f0) - mu0 * sc0;
    float sh1 = __ldg(beta + f1) - mu1 * sc1;

    // recycle state not read by this kernel: g_degi, g_scanstat
    {
        int t = blockIdx.x * 256 + threadIdx.x;       // 32768 threads
        uint4 zz = make_uint4(0u, 0u, 0u, 0u);
        *((uint4*)g_degi + t) = zz;                    // 131072 ints = 32768 uint4
        if (t < 512) g_scanstat[t] = 0ull;
    }

    float s0 = 0.f, s1 = 0.f;
    int i = s;
    for (; i + 4 <= e; i += 4) {
        float2 a0 = __half22float2(g_z2[(size_t)(i + 0) * 32 + lane]);
        float2 a1 = __half22float2(g_z2[(size_t)(i + 1) * 32 + lane]);
        float2 a2 = __half22float2(g_z2[(size_t)(i + 2) * 32 + lane]);
        float2 a3 = __half22float2(g_z2[(size_t)(i + 3) * 32 + lane]);
        s0 += fmaxf(a0.x * sc0 + sh0, 0.f) + fmaxf(a1.x * sc0 + sh0, 0.f)
            + fmaxf(a2.x * sc0 + sh0, 0.f) + fmaxf(a3.x * sc0 + sh0, 0.f);
        s1 += fmaxf(a0.y * sc1 + sh1, 0.f) + fmaxf(a1.y * sc1 + sh1, 0.f)
            + fmaxf(a2.y * sc1 + sh1, 0.f) + fmaxf(a3.y * sc1 + sh1, 0.f);
    }
    for (; i < e; i++) {
        float2 f = __half22float2(g_z2[(size_t)i * 32 + lane]);
        s0 += fmaxf(f.x * sc0 + sh0, 0.f);
        s1 += fmaxf(f.y * sc1 + sh1, 0.f);
    }
    float inv = (c > 0) ? 1.0f / (float)c : 0.f;
    float p0 = s0 * inv, p1 = s1 * inv;

    // heads: hidden unit = lane (32 units)
    float hO = __ldg(bo1 + lane), hB = __ldg(bb1 + lane);
#pragma unroll 8
    for (int i2 = 0; i2 < 32; i2++) {
        float c0 = __shfl_sync(0xffffffffu, p0, i2);
        float c1 = __shfl_sync(0xffffffffu, p1, i2);
        hO += c0 * __ldg(Wo1 + (2 * i2) * 32 + lane) + c1 * __ldg(Wo1 + (2 * i2 + 1) * 32 + lane);
        hB += c0 * __ldg(Wb1 + (2 * i2) * 32 + lane) + c1 * __ldg(Wb1 + (2 * i2 + 1) * 32 + lane);
    }
#pragma unroll
    for (int i3 = 0; i3 < G_FEAT; i3++) {
        float ci = __ldg(gf + (size_t)g * G_FEAT + i3);
        hO += ci * __ldg(Wo1 + (HID + i3) * 32 + lane);
        hB += ci * __ldg(Wb1 + (HID + i3) * 32 + lane);
    }
    hO = fmaxf(hO, 0.f);
    hB = fmaxf(hB, 0.f);
    float vO = hO * __ldg(Wo2 + lane);
    float vB = hB * __ldg(Wb2 + lane);
#pragma unroll
    for (int off = 16; off; off >>= 1) {
        vO += __shfl_down_sync(0xffffffffu, vO, off);
        vB += __shfl_down_sync(0xffffffffu, vB, off);
    }
    if (lane == 0) {
        out[g] = vO + __ldg(bo2);
        out[N_GRAPHS + g] = vB + __ldg(bb2);
    }

    // last-block ticket resets g_s2/g_q2 after every block has read them
    __syncthreads();
    if (threadIdx.x == 0) {
        int old = atomicAdd(&g_ticket, 1);
        if (old == (int)gridDim.x - 1) {
            for (int f = 0; f < HID; f++) { g_s2[f] = 0.f; g_q2[f] = 0.f; }
            g_ticket = 0;
        }
    }
}

// ---------------- launch ----------------
extern "C" void kernel_launch(void* const* d_in, const int* in_sizes, int n_in,
                              void* d_out, int out_size) {
    const float* x      = (const float*)d_in[0];
    const int*   ei     = (const int*)  d_in[1];
    const int*   batch  = (const int*)  d_in[2];
    const float* gfeat  = (const float*)d_in[3];
    const float* W1     = (const float*)d_in[4];
    const float* b1     = (const float*)d_in[5];
    const float* gamma1 = (const float*)d_in[6];
    const float* beta1  = (const float*)d_in[7];
    const float* W2     = (const float*)d_in[8];
    const float* b2     = (const float*)d_in[9];
    const float* gamma2 = (const float*)d_in[10];
    const float* beta2  = (const float*)d_in[11];
    const float* Wo1    = (const float*)d_in[12];
    const float* bo1    = (const float*)d_in[13];
    const float* Wo2    = (const float*)d_in[14];
    const float* bo2    = (const float*)d_in[15];
    const float* Wb1    = (const float*)d_in[16];
    const float* bb1    = (const float*)d_in[17];
    const float* Wb2    = (const float*)d_in[18];
    const float* bb2    = (const float*)d_in[19];
    float* out = (float*)d_out;

    float* s1; float* q1; float* s2; float* q2;
    cudaGetSymbolAddress((void**)&s1, g_s1);
    cudaGetSymbolAddress((void**)&q1, g_q1);
    cudaGetSymbolAddress((void**)&s2, g_s2);
    cudaGetSymbolAddress((void**)&q2, g_q2);
    __half2* a1; __half2* z1; __half2* a2; __half2* z2;
    cudaGetSymbolAddress((void**)&a1, g_a1);
    cudaGetSymbolAddress((void**)&z1, g_z1);
    cudaGetSymbolAddress((void**)&a2, g_a2);
    cudaGetSymbolAddress((void**)&z2, g_z2);

    deg_kernel<<<2048, 256>>>(ei, batch);       // 0
    scan_kernel<<<512, 256>>>(x);               // 1
    bucket_kernel<<<2048, 256>>>(ei);           // 2
    agg1_kernel<<<2048, 256>>>();               // 3  <- ncu capture slot
    xw_kernel<F_IN><<<N_NODES / 128, 128>>>(a1, z1, W1, b1, s1, q1);   // 4
    prep2_kernel<<<4096, 256>>>(gamma1, beta1); // 5
    agg2_kernel<<<2048, 256>>>();               // 6
    xw_kernel<HID><<<N_NODES / 128, 128>>>(a2, z2, W2, b2, s2, q2);    // 7
    poolmlp_kernel<<<128, 256>>>(gamma2, beta2, gfeat, Wo1, bo1, Wo2, bo2,
                                 Wb1, bb1, Wb2, bb2, out);             // 8
}

// round 15
// speedup vs baseline: 1.5217x; 1.5106x over previous
#include <cuda_runtime.h>
#include <cuda_fp16.h>
#include <cstdint>

#define N_NODES  131072
#define N_EDGES  2097152
#define F_IN     32
#define HID      64
#define G_FEAT   16
#define N_GRAPHS 1024
#define BN_EPS   1e-5f
#define SRT_CAP  (N_EDGES + 8 * N_NODES)

// ---------------- device scratch (zero-initialized at load; recycled each run) --------
__device__ int   g_degi[N_NODES];          // zeroed by poolmlp (end of each run)
__device__ int   g_rowstart[N_NODES];
__device__ int   g_fill[N_NODES];
__device__ int   g_srt[SRT_CAP];
__device__ unsigned long long g_scanstat[512];  // zeroed by poolmlp
__device__ float g_dinv[N_NODES];
// +1 dummy zero row at index N_NODES (never written; stays zero)
__device__ __align__(16) __half2 g_y1[(size_t)(N_NODES + 1) * 16];  // dinv*x (32 feats)
__device__ __align__(16) __half2 g_a1[(size_t)N_NODES * 16];        // dinv*agg(y1)
__device__ __align__(16) __half2 g_z1[(size_t)N_NODES * 32];        // a1@W1+b1
__device__ __align__(16) __half2 g_y2[(size_t)(N_NODES + 1) * 32];  // dinv*relu(bn(z1))
__device__ __align__(16) __half2 g_a2[(size_t)N_NODES * 32];        // dinv*agg(y2)
__device__ __align__(16) __half2 g_z2[(size_t)N_NODES * 32];        // a2@W2+b2
__device__ float g_s1[HID], g_q1[HID];     // reset by agg2 (after prep2 reads them)
__device__ float g_s2[HID], g_q2[HID];     // reset by poolmlp last-block ticket
__device__ int   g_start[N_GRAPHS + 1];
__device__ int   g_ticket;                 // reset by the same last block

__device__ __forceinline__ unsigned long long ffma2(unsigned long long a,
                                                    unsigned long long b,
                                                    unsigned long long c) {
    unsigned long long d;
    asm("fma.rn.f32x2 %0, %1, %2, %3;" : "=l"(d) : "l"(a), "l"(b), "l"(c));
    return d;
}
__device__ __forceinline__ void redf(float* p, float v) {
    asm volatile("red.global.add.f32 [%0], %1;" :: "l"(p), "f"(v) : "memory");
}

// ---------------- degree (REDG, no return) + graph-start boundaries ----------------
__global__ void deg_kernel(const int* __restrict__ ei, const int* __restrict__ batch) {
    int t = blockIdx.x * 256 + threadIdx.x;       // 524288 threads
    int4 d = __ldg((const int4*)(ei + N_EDGES) + t);
    unsigned one = 1u;
    asm volatile("red.global.add.u32 [%0], %1;" :: "l"((unsigned*)(g_degi + d.x)), "r"(one) : "memory");
    asm volatile("red.global.add.u32 [%0], %1;" :: "l"((unsigned*)(g_degi + d.y)), "r"(one) : "memory");
    asm volatile("red.global.add.u32 [%0], %1;" :: "l"((unsigned*)(g_degi + d.z)), "r"(one) : "memory");
    asm volatile("red.global.add.u32 [%0], %1;" :: "l"((unsigned*)(g_degi + d.w)), "r"(one) : "memory");
    if (t < N_NODES) {
        int b = __ldg(batch + t);
        int prev = (t == 0) ? -1 : __ldg(batch + t - 1);
        for (int g = prev + 1; g <= b; g++) g_start[g] = t;
        if (t == N_NODES - 1)
            for (int g = b + 1; g <= N_GRAPHS; g++) g_start[g] = N_NODES;
    }
}

// ---------------- single-pass scan over PADDED degrees (+self edge) + dinv + y1 ------
__global__ __launch_bounds__(256) void scan_kernel(const float* __restrict__ x) {
    __shared__ int sh[256];
    __shared__ int s_off;
    int tid = threadIdx.x;
    int bid = blockIdx.x;
    int n = bid * 256 + tid;
    int d = g_degi[n];
    int dp = (d + 8) & ~7;          // self edge + pad to multiple of 8
    sh[tid] = dp;
    __syncthreads();
#pragma unroll
    for (int off = 1; off < 256; off <<= 1) {
        int v = (tid >= off) ? sh[tid - off] : 0;
        __syncthreads();
        sh[tid] += v;
        __syncthreads();
    }
    int total = sh[255];
    if (tid == 0) {
        if (bid == 0) {
            atomicExch(&g_scanstat[0], (2ull << 32) | (unsigned)total);
            s_off = 0;
        } else {
            atomicExch(&g_scanstat[bid], (1ull << 32) | (unsigned)total);
            long long running = 0;
            int p = bid - 1;
            while (p >= 0) {
                unsigned long long st;
                do { st = atomicAdd(&g_scanstat[p], 0ull); } while ((st >> 32) == 0ull);
                running += (unsigned)st;
                if ((st >> 32) == 2ull) break;
                p--;
            }
            atomicExch(&g_scanstat[bid], (2ull << 32) | (unsigned)(running + total));
            s_off = (int)running;
        }
    }
    __syncthreads();
    int rs = s_off + sh[tid] - dp;   // exclusive prefix (padded)
    g_rowstart[n] = rs;
    g_fill[n] = rs;
    g_srt[rs + d] = n;                                     // self edge
    for (int p = d + 1; p < dp; p++) g_srt[rs + p] = N_NODES;  // dummy zero rows
    float dv = rsqrtf((float)d + 1.0f);
    g_dinv[n] = dv;
    const float4* xr = (const float4*)(x + (size_t)n * F_IN);
    uint4* yw = (uint4*)(g_y1 + (size_t)n * 16);
#pragma unroll
    for (int q = 0; q < 2; q++) {
        float4 v0 = __ldg(xr + 4 * q + 0);
        float4 v1 = __ldg(xr + 4 * q + 1);
        float4 v2 = __ldg(xr + 4 * q + 2);
        float4 v3 = __ldg(xr + 4 * q + 3);
        __half2 h0 = __floats2half2_rn(v0.x * dv, v0.y * dv);
        __half2 h1 = __floats2half2_rn(v0.z * dv, v0.w * dv);
        __half2 h2 = __floats2half2_rn(v1.x * dv, v1.y * dv);
        __half2 h3 = __floats2half2_rn(v1.z * dv, v1.w * dv);
        __half2 h4 = __floats2half2_rn(v2.x * dv, v2.y * dv);
        __half2 h5 = __floats2half2_rn(v2.z * dv, v2.w * dv);
        __half2 h6 = __floats2half2_rn(v3.x * dv, v3.y * dv);
        __half2 h7 = __floats2half2_rn(v3.z * dv, v3.w * dv);
        uint4 w0, w1;
        w0.x = *(unsigned*)&h0; w0.y = *(unsigned*)&h1;
        w0.z = *(unsigned*)&h2; w0.w = *(unsigned*)&h3;
        w1.x = *(unsigned*)&h4; w1.y = *(unsigned*)&h5;
        w1.z = *(unsigned*)&h6; w1.w = *(unsigned*)&h7;
        yw[2 * q + 0] = w0;
        yw[2 * q + 1] = w1;
    }
}

// ---------------- bucket edges by dst (vectorized atomic fill) ----------------
__global__ void bucket_kernel(const int* __restrict__ ei) {
    int e4 = blockIdx.x * 256 + threadIdx.x;
    int4 s = __ldg((const int4*)ei + e4);
    int4 d = __ldg((const int4*)(ei + N_EDGES) + e4);
    g_srt[atomicAdd(&g_fill[d.x], 1)] = s.x;
    g_srt[atomicAdd(&g_fill[d.y], 1)] = s.y;
    g_srt[atomicAdd(&g_fill[d.z], 1)] = s.z;
    g_srt[atomicAdd(&g_fill[d.w], 1)] = s.w;
}

// ---------------- CSR aggregate, layer 1: 4 nodes/warp, 8 lanes/node (8B slice) -----
__global__ __launch_bounds__(256) void agg1_kernel() {
    int warp = blockIdx.x * 8 + (threadIdx.x >> 5);
    int lane = threadIdx.x & 31;
    int sub = lane >> 3;        // node subgroup 0..3
    int sl = lane & 7;          // uint2 slice (8 per 64B row)
    const uint2* yb = (const uint2*)g_y1;   // 8 uint2 per row
#pragma unroll
    for (int rep = 0; rep < 2; rep++) {
        int n = warp * 8 + rep * 4 + sub;
        int rs = __ldg(&g_rowstart[n]);
        int degp = (__ldg(&g_degi[n]) + 8) & ~7;   // includes self + pad
        int mx = degp;
        mx = max(mx, __shfl_xor_sync(0xffffffffu, mx, 8));
        mx = max(mx, __shfl_xor_sync(0xffffffffu, mx, 16));
        __half2 zz = __float2half2_rn(0.f);
        __half2 a0 = zz, a1 = zz;
        for (int base = 0; base < mx; base += 8) {
            int idx = (base < degp) ? __ldg(&g_srt[rs + base + sl]) : (int)N_NODES;
#pragma unroll
            for (int p = 0; p < 8; p++) {
                int j = __shfl_sync(0xffffffffu, idx, (sub << 3) + p);
                uint2 u = __ldg(yb + (size_t)j * 8 + sl);
                a0 = __hadd2(a0, *(__half2*)&u.x);
                a1 = __hadd2(a1, *(__half2*)&u.y);
            }
        }
        __half2 hd = __float2half2_rn(__ldg(&g_dinv[n]));
        a0 = __hmul2(a0, hd);
        a1 = __hmul2(a1, hd);
        uint2 o;
        o.x = *(unsigned*)&a0; o.y = *(unsigned*)&a1;
        *((uint2*)g_a1 + (size_t)n * 8 + sl) = o;
    }
}

// ---------------- CSR aggregate, layer 2: 4 nodes/warp, 8 lanes/node (16B slice) ----
// Also resets g_s1/g_q1 (safe: their reader prep2 ran before this kernel).
__global__ __launch_bounds__(256) void agg2_kernel() {
    if (blockIdx.x == 0 && threadIdx.x < HID) {
        g_s1[threadIdx.x] = 0.f;
        g_q1[threadIdx.x] = 0.f;
    }
    int warp = blockIdx.x * 8 + (threadIdx.x >> 5);
    int lane = threadIdx.x & 31;
    int sub = lane >> 3;        // node subgroup 0..3
    int sl = lane & 7;          // 16B slice (8 per 128B row)
    const uint4* yb = (const uint4*)g_y2;   // 8 uint4 per row
#pragma unroll
    for (int rep = 0; rep < 2; rep++) {
        int n = warp * 8 + rep * 4 + sub;
        int rs = __ldg(&g_rowstart[n]);
        int degp = (__ldg(&g_degi[n]) + 8) & ~7;   // includes self + pad
        int mx = degp;
        mx = max(mx, __shfl_xor_sync(0xffffffffu, mx, 8));
        mx = max(mx, __shfl_xor_sync(0xffffffffu, mx, 16));
        __half2 zz = __float2half2_rn(0.f);
        __half2 a0 = zz, a1 = zz, a2 = zz, a3 = zz;
        for (int base = 0; base < mx; base += 8) {
            int idx = (base < degp) ? __ldg(&g_srt[rs + base + sl]) : (int)N_NODES;
#pragma unroll
            for (int p = 0; p < 8; p++) {
                int j = __shfl_sync(0xffffffffu, idx, (sub << 3) + p);
                uint4 u = __ldg(yb + (size_t)j * 8 + sl);
                a0 = __hadd2(a0, *(__half2*)&u.x);
                a1 = __hadd2(a1, *(__half2*)&u.y);
                a2 = __hadd2(a2, *(__half2*)&u.z);
                a3 = __hadd2(a3, *(__half2*)&u.w);
            }
        }
        __half2 hd = __float2half2_rn(__ldg(&g_dinv[n]));
        a0 = __hmul2(a0, hd);
        a1 = __hmul2(a1, hd);
        a2 = __hmul2(a2, hd);
        a3 = __hmul2(a3, hd);
        uint4 o;
        o.x = *(unsigned*)&a0; o.y = *(unsigned*)&a1;
        o.z = *(unsigned*)&a2; o.w = *(unsigned*)&a3;
        *((uint4*)g_a2 + (size_t)n * 8 + sl) = o;
    }
}

// ---------------- GEMM: z = a @ W + b ; fused BN stats ----------------
template <int K>
__global__ __launch_bounds__(128) void xw_kernel(const __half2* __restrict__ av,
                                                 __half2* __restrict__ zv,
                                                 const float* __restrict__ W,
                                                 const float* __restrict__ b,
                                                 float* __restrict__ sArr,
                                                 float* __restrict__ qArr) {
    __shared__ __align__(16) float sW[K * HID];
    __shared__ __half2 sOut[128][33];
    __shared__ float ps[4][64], pq[4][64];
    int tid = threadIdx.x;
    for (int i = tid; i < K * HID; i += 128) sW[i] = W[i];
    __syncthreads();
    int n = blockIdx.x * 128 + tid;
    float in[K];
    {
        const uint4* r = (const uint4*)(av + (size_t)n * (K / 2));
#pragma unroll
        for (int q = 0; q < K / 8; q++) {
            uint4 u = __ldg(r + q);
            unsigned uu[4] = {u.x, u.y, u.z, u.w};
#pragma unroll
            for (int m = 0; m < 4; m++) {
                float2 f = __half22float2(*(__half2*)&uu[m]);
                in[8 * q + 2 * m + 0] = f.x;
                in[8 * q + 2 * m + 1] = f.y;
            }
        }
    }
#pragma unroll 1
    for (int jb = 0; jb < 4; jb++) {
        unsigned long long acc[8];
#pragma unroll
        for (int m = 0; m < 8; m++) acc[m] = 0ull;
#pragma unroll 4
        for (int k = 0; k < K; k++) {
            unsigned long long xp;
            asm("mov.b64 %0, {%1, %1};" : "=l"(xp) : "r"(__float_as_uint(in[k])));
            const ulonglong2* wp = (const ulonglong2*)(sW + k * HID + jb * 16);
            ulonglong2 w01 = wp[0], w23 = wp[1], w45 = wp[2], w67 = wp[3];
            acc[0] = ffma2(xp, w01.x, acc[0]);
            acc[1] = ffma2(xp, w01.y, acc[1]);
            acc[2] = ffma2(xp, w23.x, acc[2]);
            acc[3] = ffma2(xp, w23.y, acc[3]);
            acc[4] = ffma2(xp, w45.x, acc[4]);
            acc[5] = ffma2(xp, w45.y, acc[5]);
            acc[6] = ffma2(xp, w67.x, acc[6]);
            acc[7] = ffma2(xp, w67.y, acc[7]);
        }
#pragma unroll
        for (int m = 0; m < 8; m++) {
            float lo, hi;
            asm("mov.b64 {%0, %1}, %2;" : "=f"(lo), "=f"(hi) : "l"(acc[m]));
            int f0 = jb * 16 + 2 * m;
            sOut[tid][jb * 8 + m] = __floats2half2_rn(lo + __ldg(b + f0),
                                                      hi + __ldg(b + f0 + 1));
        }
    }
    __syncthreads();
    unsigned* dst = (unsigned*)(zv + (size_t)blockIdx.x * 128 * 32);
    const unsigned* srcBase = (const unsigned*)sOut;
#pragma unroll
    for (int i = tid; i < 4096; i += 128) {
        int node = i >> 5, c = i & 31;
        dst[i] = srcBase[node * 33 + c];
    }
    {
        int c = tid & 31, part = tid >> 5;
        float s0 = 0.f, s1 = 0.f, q0 = 0.f, q1 = 0.f;
#pragma unroll 4
        for (int m = 0; m < 32; m++) {
            float2 f = __half22float2(sOut[part * 32 + m][c]);
            s0 += f.x; s1 += f.y; q0 += f.x * f.x; q1 += f.y * f.y;
        }
        ps[part][2 * c] = s0; ps[part][2 * c + 1] = s1;
        pq[part][2 * c] = q0; pq[part][2 * c + 1] = q1;
    }
    __syncthreads();
    if (tid < 64) {
        float s = ps[0][tid] + ps[1][tid] + ps[2][tid] + ps[3][tid];
        float q = pq[0][tid] + pq[1][tid] + pq[2][tid] + pq[3][tid];
        redf(sArr + tid, s);
        redf(qArr + tid, q);
    }
}

// ---------------- prep2: y2 = fp16(dinv * relu(bn1(z1))) ----------------
__global__ __launch_bounds__(256) void prep2_kernel(const float* __restrict__ gamma,
                                                    const float* __restrict__ beta) {
    __shared__ float sc[HID], sh[HID];
    int tid = threadIdx.x;
    if (tid < HID) {
        const float inv_n = 1.0f / (float)N_NODES;
        float mu = g_s1[tid] * inv_n;
        float var = g_q1[tid] * inv_n - mu * mu;
        float rstd = rsqrtf(var + BN_EPS);
        float s = rstd * __ldg(gamma + tid);
        sc[tid] = s;
        sh[tid] = __ldg(beta + tid) - mu * s;
    }
    __syncthreads();
    int i4 = blockIdx.x * 256 + tid;
    int n = i4 >> 3;
    int fb = (i4 & 7) * 8;
    float d = __ldg(&g_dinv[n]);
    uint4 u = *((const uint4*)g_z1 + i4);
    unsigned uu[4] = {u.x, u.y, u.z, u.w};
    uint4 o;
    unsigned* oo = (unsigned*)&o;
#pragma unroll
    for (int m = 0; m < 4; m++) {
        float2 f = __half22float2(*(__half2*)&uu[m]);
        int f0 = fb + 2 * m;
        float y0 = fmaxf(f.x * sc[f0] + sh[f0], 0.f) * d;
        float y1 = fmaxf(f.y * sc[f0 + 1] + sh[f0 + 1], 0.f) * d;
        __half2 h = __floats2half2_rn(y0, y1);
        oo[m] = *(unsigned*)&h;
    }
    *((uint4*)g_y2 + i4) = o;
}

// ---------------- fused pool + MLP heads + state recycling ----------------
__global__ __launch_bounds__(256) void poolmlp_kernel(
    const float* __restrict__ gamma, const float* __restrict__ beta,
    const float* __restrict__ gf,
    const float* __restrict__ Wo1, const float* __restrict__ bo1,
    const float* __restrict__ Wo2, const float* __restrict__ bo2,
    const float* __restrict__ Wb1, const float* __restrict__ bb1,
    const float* __restrict__ Wb2, const float* __restrict__ bb2,
    float* __restrict__ out) {
    int g = (blockIdx.x * 256 + threadIdx.x) >> 5;
    int lane = threadIdx.x & 31;
    int s = g_start[g], e = g_start[g + 1];
    int c = e - s;
    const float inv_n = 1.0f / (float)N_NODES;
    int f0 = 2 * lane, f1 = 2 * lane + 1;
    float mu0 = g_s2[f0] * inv_n, mu1 = g_s2[f1] * inv_n;
    float v0 = g_q2[f0] * inv_n - mu0 * mu0;
    float v1 = g_q2[f1] * inv_n - mu1 * mu1;
    float sc0 = rsqrtf(v0 + BN_EPS) * __ldg(gamma + f0);
    float sc1 = rsqrtf(v1 + BN_EPS) * __ldg(gamma + f1);
    float sh0 = __ldg(beta + f0) - mu0 * sc0;
    float sh1 = __ldg(beta + f1) - mu1 * sc1;

    // recycle state not read by this kernel: g_degi, g_scanstat
    {
        int t = blockIdx.x * 256 + threadIdx.x;       // 32768 threads
        uint4 zz = make_uint4(0u, 0u, 0u, 0u);
        *((uint4*)g_degi + t) = zz;                    // 131072 ints = 32768 uint4
        if (t < 512) g_scanstat[t] = 0ull;
    }

    float s0 = 0.f, s1 = 0.f;
    int i = s;
    for (; i + 4 <= e; i += 4) {
        float2 a0 = __half22float2(g_z2[(size_t)(i + 0) * 32 + lane]);
        float2 a1 = __half22float2(g_z2[(size_t)(i + 1) * 32 + lane]);
        float2 a2 = __half22float2(g_z2[(size_t)(i + 2) * 32 + lane]);
        float2 a3 = __half22float2(g_z2[(size_t)(i + 3) * 32 + lane]);
        s0 += fmaxf(a0.x * sc0 + sh0, 0.f) + fmaxf(a1.x * sc0 + sh0, 0.f)
            + fmaxf(a2.x * sc0 + sh0, 0.f) + fmaxf(a3.x * sc0 + sh0, 0.f);
        s1 += fmaxf(a0.y * sc1 + sh1, 0.f) + fmaxf(a1.y * sc1 + sh1, 0.f)
            + fmaxf(a2.y * sc1 + sh1, 0.f) + fmaxf(a3.y * sc1 + sh1, 0.f);
    }
    for (; i < e; i++) {
        float2 f = __half22float2(g_z2[(size_t)i * 32 + lane]);
        s0 += fmaxf(f.x * sc0 + sh0, 0.f);
        s1 += fmaxf(f.y * sc1 + sh1, 0.f);
    }
    float inv = (c > 0) ? 1.0f / (float)c : 0.f;
    float p0 = s0 * inv, p1 = s1 * inv;

    // heads: hidden unit = lane (32 units)
    float hO = __ldg(bo1 + lane), hB = __ldg(bb1 + lane);
#pragma unroll 8
    for (int i2 = 0; i2 < 32; i2++) {
        float c0 = __shfl_sync(0xffffffffu, p0, i2);
        float c1 = __shfl_sync(0xffffffffu, p1, i2);
        hO += c0 * __ldg(Wo1 + (2 * i2) * 32 + lane) + c1 * __ldg(Wo1 + (2 * i2 + 1) * 32 + lane);
        hB += c0 * __ldg(Wb1 + (2 * i2) * 32 + lane) + c1 * __ldg(Wb1 + (2 * i2 + 1) * 32 + lane);
    }
#pragma unroll
    for (int i3 = 0; i3 < G_FEAT; i3++) {
        float ci = __ldg(gf + (size_t)g * G_FEAT + i3);
        hO += ci * __ldg(Wo1 + (HID + i3) * 32 + lane);
        hB += ci * __ldg(Wb1 + (HID + i3) * 32 + lane);
    }
    hO = fmaxf(hO, 0.f);
    hB = fmaxf(hB, 0.f);
    float vO = hO * __ldg(Wo2 + lane);
    float vB = hB * __ldg(Wb2 + lane);
#pragma unroll
    for (int off = 16; off; off >>= 1) {
        vO += __shfl_down_sync(0xffffffffu, vO, off);
        vB += __shfl_down_sync(0xffffffffu, vB, off);
    }
    if (lane == 0) {
        out[g] = vO + __ldg(bo2);
        out[N_GRAPHS + g] = vB + __ldg(bb2);
    }

    // last-block ticket resets g_s2/g_q2 after every block has read them
    __syncthreads();
    if (threadIdx.x == 0) {
        int old = atomicAdd(&g_ticket, 1);
        if (old == (int)gridDim.x - 1) {
            for (int f = 0; f < HID; f++) { g_s2[f] = 0.f; g_q2[f] = 0.f; }
            g_ticket = 0;
        }
    }
}

// ---------------- launch ----------------
extern "C" void kernel_launch(void* const* d_in, const int* in_sizes, int n_in,
                              void* d_out, int out_size) {
    const float* x      = (const float*)d_in[0];
    const int*   ei     = (const int*)  d_in[1];
    const int*   batch  = (const int*)  d_in[2];
    const float* gfeat  = (const float*)d_in[3];
    const float* W1     = (const float*)d_in[4];
    const float* b1     = (const float*)d_in[5];
    const float* gamma1 = (const float*)d_in[6];
    const float* beta1  = (const float*)d_in[7];
    const float* W2     = (const float*)d_in[8];
    const float* b2     = (const float*)d_in[9];
    const float* gamma2 = (const float*)d_in[10];
    const float* beta2  = (const float*)d_in[11];
    const float* Wo1    = (const float*)d_in[12];
    const float* bo1    = (const float*)d_in[13];
    const float* Wo2    = (const float*)d_in[14];
    const float* bo2    = (const float*)d_in[15];
    const float* Wb1    = (const float*)d_in[16];
    const float* bb1    = (const float*)d_in[17];
    const float* Wb2    = (const float*)d_in[18];
    const float* bb2    = (const float*)d_in[19];
    float* out = (float*)d_out;

    float* s1; float* q1; float* s2; float* q2;
    cudaGetSymbolAddress((void**)&s1, g_s1);
    cudaGetSymbolAddress((void**)&q1, g_q1);
    cudaGetSymbolAddress((void**)&s2, g_s2);
    cudaGetSymbolAddress((void**)&q2, g_q2);
    __half2* a1; __half2* z1; __half2* a2; __half2* z2;
    cudaGetSymbolAddress((void**)&a1, g_a1);
    cudaGetSymbolAddress((void**)&z1, g_z1);
    cudaGetSymbolAddress((void**)&a2, g_a2);
    cudaGetSymbolAddress((void**)&z2, g_z2);

    deg_kernel<<<2048, 256>>>(ei, batch);       // 0
    scan_kernel<<<512, 256>>>(x);               // 1
    bucket_kernel<<<2048, 256>>>(ei);           // 2
    agg1_kernel<<<2048, 256>>>();               // 3  <- ncu capture slot
    xw_kernel<F_IN><<<N_NODES / 128, 128>>>(a1, z1, W1, b1, s1, q1);   // 4
    prep2_kernel<<<4096, 256>>>(gamma1, beta1); // 5
    agg2_kernel<<<2048, 256>>>();               // 6
    xw_kernel<HID><<<N_NODES / 128, 128>>>(a2, z2, W2, b2, s2, q2);    // 7
    poolmlp_kernel<<<128, 256>>>(gamma2, beta2, gfeat, Wo1, bo1, Wo2, bo2,
                                 Wb1, bb1, Wb2, bb2, out);             // 8
}

// round 16
// speedup vs baseline: 1.5246x; 1.0019x over previous
#include <cuda_runtime.h>
#include <cuda_fp16.h>
#include <cstdint>

#define N_NODES  131072
#define N_EDGES  2097152
#define F_IN     32
#define HID      64
#define G_FEAT   16
#define N_GRAPHS 1024
#define BN_EPS   1e-5f
#define SRT_CAP  (N_EDGES + 8 * N_NODES)

// ---------------- device scratch (zero-initialized at load; recycled each run) --------
__device__ int   g_degi[N_NODES];          // zeroed by poolmlp (end of each run)
__device__ int   g_rowstart[N_NODES];
__device__ int   g_fill[N_NODES];
__device__ int   g_srt[SRT_CAP];
__device__ unsigned long long g_scanstat[512];  // zeroed by poolmlp
__device__ float g_dinv[N_NODES];
// +1 dummy zero row at index N_NODES (never written; stays zero)
__device__ __align__(16) __half2 g_y1[(size_t)(N_NODES + 1) * 16];  // dinv*x (32 feats)
__device__ __align__(16) __half2 g_a1[(size_t)N_NODES * 16];        // dinv*agg(y1)
__device__ __align__(16) __half2 g_z1[(size_t)N_NODES * 32];        // a1@W1+b1
__device__ __align__(16) __half2 g_y2[(size_t)(N_NODES + 1) * 32];  // dinv*relu(bn(z1))
__device__ __align__(16) __half2 g_a2[(size_t)N_NODES * 32];        // dinv*agg(y2)
__device__ __align__(16) __half2 g_z2[(size_t)N_NODES * 32];        // a2@W2+b2
__device__ float g_s1[HID], g_q1[HID];     // reset by agg2 (after prep2 reads them)
__device__ float g_s2[HID], g_q2[HID];     // reset by poolmlp last-block ticket
__device__ int   g_start[N_GRAPHS + 1];
__device__ int   g_ticket;                 // reset by the same last block

__device__ __forceinline__ unsigned long long ffma2(unsigned long long a,
                                                    unsigned long long b,
                                                    unsigned long long c) {
    unsigned long long d;
    asm("fma.rn.f32x2 %0, %1, %2, %3;" : "=l"(d) : "l"(a), "l"(b), "l"(c));
    return d;
}
__device__ __forceinline__ void redf(float* p, float v) {
    asm volatile("red.global.add.f32 [%0], %1;" :: "l"(p), "f"(v) : "memory");
}

// ---------------- degree (REDG, no return) + graph-start boundaries ----------------
__global__ void deg_kernel(const int* __restrict__ ei, const int* __restrict__ batch) {
    int t = blockIdx.x * 256 + threadIdx.x;       // 524288 threads
    int4 d = __ldg((const int4*)(ei + N_EDGES) + t);
    unsigned one = 1u;
    asm volatile("red.global.add.u32 [%0], %1;" :: "l"((unsigned*)(g_degi + d.x)), "r"(one) : "memory");
    asm volatile("red.global.add.u32 [%0], %1;" :: "l"((unsigned*)(g_degi + d.y)), "r"(one) : "memory");
    asm volatile("red.global.add.u32 [%0], %1;" :: "l"((unsigned*)(g_degi + d.z)), "r"(one) : "memory");
    asm volatile("red.global.add.u32 [%0], %1;" :: "l"((unsigned*)(g_degi + d.w)), "r"(one) : "memory");
    if (t < N_NODES) {
        int b = __ldg(batch + t);
        int prev = (t == 0) ? -1 : __ldg(batch + t - 1);
        for (int g = prev + 1; g <= b; g++) g_start[g] = t;
        if (t == N_NODES - 1)
            for (int g = b + 1; g <= N_GRAPHS; g++) g_start[g] = N_NODES;
    }
}

// ---------------- single-pass scan over PADDED degrees (+self edge) + dinv + y1 ------
__global__ __launch_bounds__(256) void scan_kernel(const float* __restrict__ x) {
    __shared__ int sh[256];
    __shared__ int s_off;
    int tid = threadIdx.x;
    int bid = blockIdx.x;
    int n = bid * 256 + tid;
    int d = g_degi[n];
    int dp = (d + 8) & ~7;          // self edge + pad to multiple of 8
    sh[tid] = dp;
    __syncthreads();
#pragma unroll
    for (int off = 1; off < 256; off <<= 1) {
        int v = (tid >= off) ? sh[tid - off] : 0;
        __syncthreads();
        sh[tid] += v;
        __syncthreads();
    }
    int total = sh[255];
    if (tid == 0) {
        if (bid == 0) {
            atomicExch(&g_scanstat[0], (2ull << 32) | (unsigned)total);
            s_off = 0;
        } else {
            atomicExch(&g_scanstat[bid], (1ull << 32) | (unsigned)total);
            long long running = 0;
            int p = bid - 1;
            while (p >= 0) {
                unsigned long long st;
                do { st = atomicAdd(&g_scanstat[p], 0ull); } while ((st >> 32) == 0ull);
                running += (unsigned)st;
                if ((st >> 32) == 2ull) break;
                p--;
            }
            atomicExch(&g_scanstat[bid], (2ull << 32) | (unsigned)(running + total));
            s_off = (int)running;
        }
    }
    __syncthreads();
    int rs = s_off + sh[tid] - dp;   // exclusive prefix (padded)
    g_rowstart[n] = rs;
    g_fill[n] = rs;
    g_srt[rs + d] = n;                                     // self edge
    for (int p = d + 1; p < dp; p++) g_srt[rs + p] = N_NODES;  // dummy zero rows
    float dv = rsqrtf((float)d + 1.0f);
    g_dinv[n] = dv;
    const float4* xr = (const float4*)(x + (size_t)n * F_IN);
    uint4* yw = (uint4*)(g_y1 + (size_t)n * 16);
#pragma unroll
    for (int q = 0; q < 2; q++) {
        float4 v0 = __ldg(xr + 4 * q + 0);
        float4 v1 = __ldg(xr + 4 * q + 1);
        float4 v2 = __ldg(xr + 4 * q + 2);
        float4 v3 = __ldg(xr + 4 * q + 3);
        __half2 h0 = __floats2half2_rn(v0.x * dv, v0.y * dv);
        __half2 h1 = __floats2half2_rn(v0.z * dv, v0.w * dv);
        __half2 h2 = __floats2half2_rn(v1.x * dv, v1.y * dv);
        __half2 h3 = __floats2half2_rn(v1.z * dv, v1.w * dv);
        __half2 h4 = __floats2half2_rn(v2.x * dv, v2.y * dv);
        __half2 h5 = __floats2half2_rn(v2.z * dv, v2.w * dv);
        __half2 h6 = __floats2half2_rn(v3.x * dv, v3.y * dv);
        __half2 h7 = __floats2half2_rn(v3.z * dv, v3.w * dv);
        uint4 w0, w1;
        w0.x = *(unsigned*)&h0; w0.y = *(unsigned*)&h1;
        w0.z = *(unsigned*)&h2; w0.w = *(unsigned*)&h3;
        w1.x = *(unsigned*)&h4; w1.y = *(unsigned*)&h5;
        w1.z = *(unsigned*)&h6; w1.w = *(unsigned*)&h7;
        yw[2 * q + 0] = w0;
        yw[2 * q + 1] = w1;
    }
}

// ---------------- bucket edges by dst (vectorized atomic fill) ----------------
__global__ void bucket_kernel(const int* __restrict__ ei) {
    int e4 = blockIdx.x * 256 + threadIdx.x;
    int4 s = __ldg((const int4*)ei + e4);
    int4 d = __ldg((const int4*)(ei + N_EDGES) + e4);
    g_srt[atomicAdd(&g_fill[d.x], 1)] = s.x;
    g_srt[atomicAdd(&g_fill[d.y], 1)] = s.y;
    g_srt[atomicAdd(&g_fill[d.z], 1)] = s.z;
    g_srt[atomicAdd(&g_fill[d.w], 1)] = s.w;
}

// ---------------- CSR aggregate, layer 1: 4 nodes/warp, 8 lanes/node ---------------
// Dual accumulator banks + software-pipelined index load.
__global__ __launch_bounds__(256) void agg1_kernel() {
    int warp = blockIdx.x * 8 + (threadIdx.x >> 5);
    int lane = threadIdx.x & 31;
    int sub = lane >> 3;        // node subgroup 0..3
    int sl = lane & 7;          // uint2 slice (8 per 64B row)
    const uint2* yb = (const uint2*)g_y1;   // 8 uint2 per row
#pragma unroll
    for (int rep = 0; rep < 2; rep++) {
        int n = warp * 8 + rep * 4 + sub;
        int rs = __ldg(&g_rowstart[n]);
        int degp = (__ldg(&g_degi[n]) + 8) & ~7;   // includes self + pad (>= 8)
        int mx = degp;
        mx = max(mx, __shfl_xor_sync(0xffffffffu, mx, 8));
        mx = max(mx, __shfl_xor_sync(0xffffffffu, mx, 16));
        __half2 zz = __float2half2_rn(0.f);
        __half2 a0 = zz, a1 = zz, b0 = zz, b1 = zz;
        int idx = __ldg(&g_srt[rs + sl]);          // window 0 always valid
        for (int base = 0; base < mx; base += 8) {
            int nb = base + 8;
            int idxn = 0;
            if (nb < mx) idxn = (nb < degp) ? __ldg(&g_srt[rs + nb + sl]) : (int)N_NODES;
#pragma unroll
            for (int p = 0; p < 8; p += 2) {
                int j0 = __shfl_sync(0xffffffffu, idx, (sub << 3) + p);
                int j1 = __shfl_sync(0xffffffffu, idx, (sub << 3) + p + 1);
                uint2 u0 = __ldg(yb + (size_t)j0 * 8 + sl);
                uint2 u1 = __ldg(yb + (size_t)j1 * 8 + sl);
                a0 = __hadd2(a0, *(__half2*)&u0.x);
                a1 = __hadd2(a1, *(__half2*)&u0.y);
                b0 = __hadd2(b0, *(__half2*)&u1.x);
                b1 = __hadd2(b1, *(__half2*)&u1.y);
            }
            idx = idxn;
        }
        a0 = __hadd2(a0, b0);
        a1 = __hadd2(a1, b1);
        __half2 hd = __float2half2_rn(__ldg(&g_dinv[n]));
        a0 = __hmul2(a0, hd);
        a1 = __hmul2(a1, hd);
        uint2 o;
        o.x = *(unsigned*)&a0; o.y = *(unsigned*)&a1;
        *((uint2*)g_a1 + (size_t)n * 8 + sl) = o;
    }
}

// ---------------- CSR aggregate, layer 2: 4 nodes/warp, 8 lanes/node ---------------
// Dual banks + pipelined index; also resets g_s1/g_q1.
__global__ __launch_bounds__(256) void agg2_kernel() {
    if (blockIdx.x == 0 && threadIdx.x < HID) {
        g_s1[threadIdx.x] = 0.f;
        g_q1[threadIdx.x] = 0.f;
    }
    int warp = blockIdx.x * 8 + (threadIdx.x >> 5);
    int lane = threadIdx.x & 31;
    int sub = lane >> 3;        // node subgroup 0..3
    int sl = lane & 7;          // 16B slice (8 per 128B row)
    const uint4* yb = (const uint4*)g_y2;   // 8 uint4 per row
#pragma unroll
    for (int rep = 0; rep < 2; rep++) {
        int n = warp * 8 + rep * 4 + sub;
        int rs = __ldg(&g_rowstart[n]);
        int degp = (__ldg(&g_degi[n]) + 8) & ~7;   // includes self + pad
        int mx = degp;
        mx = max(mx, __shfl_xor_sync(0xffffffffu, mx, 8));
        mx = max(mx, __shfl_xor_sync(0xffffffffu, mx, 16));
        __half2 zz = __float2half2_rn(0.f);
        __half2 a0 = zz, a1 = zz, a2 = zz, a3 = zz;
        __half2 b0 = zz, b1 = zz, b2 = zz, b3 = zz;
        int idx = __ldg(&g_srt[rs + sl]);
        for (int base = 0; base < mx; base += 8) {
            int nb = base + 8;
            int idxn = 0;
            if (nb < mx) idxn = (nb < degp) ? __ldg(&g_srt[rs + nb + sl]) : (int)N_NODES;
#pragma unroll
            for (int p = 0; p < 8; p += 2) {
                int j0 = __shfl_sync(0xffffffffu, idx, (sub << 3) + p);
                int j1 = __shfl_sync(0xffffffffu, idx, (sub << 3) + p + 1);
                uint4 u0 = __ldg(yb + (size_t)j0 * 8 + sl);
                uint4 u1 = __ldg(yb + (size_t)j1 * 8 + sl);
                a0 = __hadd2(a0, *(__half2*)&u0.x);
                a1 = __hadd2(a1, *(__half2*)&u0.y);
                a2 = __hadd2(a2, *(__half2*)&u0.z);
                a3 = __hadd2(a3, *(__half2*)&u0.w);
                b0 = __hadd2(b0, *(__half2*)&u1.x);
                b1 = __hadd2(b1, *(__half2*)&u1.y);
                b2 = __hadd2(b2, *(__half2*)&u1.z);
                b3 = __hadd2(b3, *(__half2*)&u1.w);
            }
            idx = idxn;
        }
        a0 = __hadd2(a0, b0);
        a1 = __hadd2(a1, b1);
        a2 = __hadd2(a2, b2);
        a3 = __hadd2(a3, b3);
        __half2 hd = __float2half2_rn(__ldg(&g_dinv[n]));
        a0 = __hmul2(a0, hd);
        a1 = __hmul2(a1, hd);
        a2 = __hmul2(a2, hd);
        a3 = __hmul2(a3, hd);
        uint4 o;
        o.x = *(unsigned*)&a0; o.y = *(unsigned*)&a1;
        o.z = *(unsigned*)&a2; o.w = *(unsigned*)&a3;
        *((uint4*)g_a2 + (size_t)n * 8 + sl) = o;
    }
}

// ---------------- GEMM: z = a @ W + b ; fused BN stats ----------------
template <int K>
__global__ __launch_bounds__(128) void xw_kernel(const __half2* __restrict__ av,
                                                 __half2* __restrict__ zv,
                                                 const float* __restrict__ W,
                                                 const float* __restrict__ b,
                                                 float* __restrict__ sArr,
                                                 float* __restrict__ qArr) {
    __shared__ __align__(16) float sW[K * HID];
    __shared__ __half2 sOut[128][33];
    __shared__ float ps[4][64], pq[4][64];
    int tid = threadIdx.x;
    for (int i = tid; i < K * HID; i += 128) sW[i] = W[i];
    __syncthreads();
    int n = blockIdx.x * 128 + tid;
    float in[K];
    {
        const uint4* r = (const uint4*)(av + (size_t)n * (K / 2));
#pragma unroll
        for (int q = 0; q < K / 8; q++) {
            uint4 u = __ldg(r + q);
            unsigned uu[4] = {u.x, u.y, u.z, u.w};
#pragma unroll
            for (int m = 0; m < 4; m++) {
                float2 f = __half22float2(*(__half2*)&uu[m]);
                in[8 * q + 2 * m + 0] = f.x;
                in[8 * q + 2 * m + 1] = f.y;
            }
        }
    }
#pragma unroll 1
    for (int jb = 0; jb < 4; jb++) {
        unsigned long long acc[8];
#pragma unroll
        for (int m = 0; m < 8; m++) acc[m] = 0ull;
#pragma unroll 4
        for (int k = 0; k < K; k++) {
            unsigned long long xp;
            asm("mov.b64 %0, {%1, %1};" : "=l"(xp) : "r"(__float_as_uint(in[k])));
            const ulonglong2* wp = (const ulonglong2*)(sW + k * HID + jb * 16);
            ulonglong2 w01 = wp[0], w23 = wp[1], w45 = wp[2], w67 = wp[3];
            acc[0] = ffma2(xp, w01.x, acc[0]);
            acc[1] = ffma2(xp, w01.y, acc[1]);
            acc[2] = ffma2(xp, w23.x, acc[2]);
            acc[3] = ffma2(xp, w23.y, acc[3]);
            acc[4] = ffma2(xp, w45.x, acc[4]);
            acc[5] = ffma2(xp, w45.y, acc[5]);
            acc[6] = ffma2(xp, w67.x, acc[6]);
            acc[7] = ffma2(xp, w67.y, acc[7]);
        }
#pragma unroll
        for (int m = 0; m < 8; m++) {
            float lo, hi;
            asm("mov.b64 {%0, %1}, %2;" : "=f"(lo), "=f"(hi) : "l"(acc[m]));
            int f0 = jb * 16 + 2 * m;
            sOut[tid][jb * 8 + m] = __floats2half2_rn(lo + __ldg(b + f0),
                                                      hi + __ldg(b + f0 + 1));
        }
    }
    __syncthreads();
    unsigned* dst = (unsigned*)(zv + (size_t)blockIdx.x * 128 * 32);
    const unsigned* srcBase = (const unsigned*)sOut;
#pragma unroll
    for (int i = tid; i < 4096; i += 128) {
        int node = i >> 5, c = i & 31;
        dst[i] = srcBase[node * 33 + c];
    }
    {
        int c = tid & 31, part = tid >> 5;
        float s0 = 0.f, s1 = 0.f, q0 = 0.f, q1 = 0.f;
#pragma unroll 4
        for (int m = 0; m < 32; m++) {
            float2 f = __half22float2(sOut[part * 32 + m][c]);
            s0 += f.x; s1 += f.y; q0 += f.x * f.x; q1 += f.y * f.y;
        }
        ps[part][2 * c] = s0; ps[part][2 * c + 1] = s1;
        pq[part][2 * c] = q0; pq[part][2 * c + 1] = q1;
    }
    __syncthreads();
    if (tid < 64) {
        float s = ps[0][tid] + ps[1][tid] + ps[2][tid] + ps[3][tid];
        float q = pq[0][tid] + pq[1][tid] + pq[2][tid] + pq[3][tid];
        redf(sArr + tid, s);
        redf(qArr + tid, q);
    }
}

// ---------------- prep2: y2 = fp16(dinv * relu(bn1(z1))) ----------------
__global__ __launch_bounds__(256) void prep2_kernel(const float* __restrict__ gamma,
                                                    const float* __restrict__ beta) {
    __shared__ float sc[HID], sh[HID];
    int tid = threadIdx.x;
    if (tid < HID) {
        const float inv_n = 1.0f / (float)N_NODES;
        float mu = g_s1[tid] * inv_n;
        float var = g_q1[tid] * inv_n - mu * mu;
        float rstd = rsqrtf(var + BN_EPS);
        float s = rstd * __ldg(gamma + tid);
        sc[tid] = s;
        sh[tid] = __ldg(beta + tid) - mu * s;
    }
    __syncthreads();
    int i4 = blockIdx.x * 256 + tid;
    int n = i4 >> 3;
    int fb = (i4 & 7) * 8;
    float d = __ldg(&g_dinv[n]);
    uint4 u = *((const uint4*)g_z1 + i4);
    unsigned uu[4] = {u.x, u.y, u.z, u.w};
    uint4 o;
    unsigned* oo = (unsigned*)&o;
#pragma unroll
    for (int m = 0; m < 4; m++) {
        float2 f = __half22float2(*(__half2*)&uu[m]);
        int f0 = fb + 2 * m;
        float y0 = fmaxf(f.x * sc[f0] + sh[f0], 0.f) * d;
        float y1 = fmaxf(f.y * sc[f0 + 1] + sh[f0 + 1], 0.f) * d;
        __half2 h = __floats2half2_rn(y0, y1);
        oo[m] = *(unsigned*)&h;
    }
    *((uint4*)g_y2 + i4) = o;
}

// ---------------- fused pool + MLP heads + state recycling ----------------
__global__ __launch_bounds__(256) void poolmlp_kernel(
    const float* __restrict__ gamma, const float* __restrict__ beta,
    const float* __restrict__ gf,
    const float* __restrict__ Wo1, const float* __restrict__ bo1,
    const float* __restrict__ Wo2, const float* __restrict__ bo2,
    const float* __restrict__ Wb1, const float* __restrict__ bb1,
    const float* __restrict__ Wb2, const float* __restrict__ bb2,
    float* __restrict__ out) {
    int g = (blockIdx.x * 256 + threadIdx.x) >> 5;
    int lane = threadIdx.x & 31;
    int s = g_start[g], e = g_start[g + 1];
    int c = e - s;
    const float inv_n = 1.0f / (float)N_NODES;
    int f0 = 2 * lane, f1 = 2 * lane + 1;
    float mu0 = g_s2[f0] * inv_n, mu1 = g_s2[f1] * inv_n;
    float v0 = g_q2[f0] * inv_n - mu0 * mu0;
    float v1 = g_q2[f1] * inv_n - mu1 * mu1;
    float sc0 = rsqrtf(v0 + BN_EPS) * __ldg(gamma + f0);
    float sc1 = rsqrtf(v1 + BN_EPS) * __ldg(gamma + f1);
    float sh0 = __ldg(beta + f0) - mu0 * sc0;
    float sh1 = __ldg(beta + f1) - mu1 * sc1;

    // recycle state not read by this kernel: g_degi, g_scanstat
    {
        int t = blockIdx.x * 256 + threadIdx.x;       // 32768 threads
        uint4 zz = make_uint4(0u, 0u, 0u, 0u);
        *((uint4*)g_degi + t) = zz;                    // 131072 ints = 32768 uint4
        if (t < 512) g_scanstat[t] = 0ull;
    }

    float s0 = 0.f, s1 = 0.f;
    int i = s;
    for (; i + 4 <= e; i += 4) {
        float2 a0 = __half22float2(g_z2[(size_t)(i + 0) * 32 + lane]);
        float2 a1 = __half22float2(g_z2[(size_t)(i + 1) * 32 + lane]);
        float2 a2 = __half22float2(g_z2[(size_t)(i + 2) * 32 + lane]);
        float2 a3 = __half22float2(g_z2[(size_t)(i + 3) * 32 + lane]);
        s0 += fmaxf(a0.x * sc0 + sh0, 0.f) + fmaxf(a1.x * sc0 + sh0, 0.f)
            + fmaxf(a2.x * sc0 + sh0, 0.f) + fmaxf(a3.x * sc0 + sh0, 0.f);
        s1 += fmaxf(a0.y * sc1 + sh1, 0.f) + fmaxf(a1.y * sc1 + sh1, 0.f)
            + fmaxf(a2.y * sc1 + sh1, 0.f) + fmaxf(a3.y * sc1 + sh1, 0.f);
    }
    for (; i < e; i++) {
        float2 f = __half22float2(g_z2[(size_t)i * 32 + lane]);
        s0 += fmaxf(f.x * sc0 + sh0, 0.f);
        s1 += fmaxf(f.y * sc1 + sh1, 0.f);
    }
    float inv = (c > 0) ? 1.0f / (float)c : 0.f;
    float p0 = s0 * inv, p1 = s1 * inv;

    // heads: hidden unit = lane (32 units)
    float hO = __ldg(bo1 + lane), hB = __ldg(bb1 + lane);
#pragma unroll 8
    for (int i2 = 0; i2 < 32; i2++) {
        float c0 = __shfl_sync(0xffffffffu, p0, i2);
        float c1 = __shfl_sync(0xffffffffu, p1, i2);
        hO += c0 * __ldg(Wo1 + (2 * i2) * 32 + lane) + c1 * __ldg(Wo1 + (2 * i2 + 1) * 32 + lane);
        hB += c0 * __ldg(Wb1 + (2 * i2) * 32 + lane) + c1 * __ldg(Wb1 + (2 * i2 + 1) * 32 + lane);
    }
#pragma unroll
    for (int i3 = 0; i3 < G_FEAT; i3++) {
        float ci = __ldg(gf + (size_t)g * G_FEAT + i3);
        hO += ci * __ldg(Wo1 + (HID + i3) * 32 + lane);
        hB += ci * __ldg(Wb1 + (HID + i3) * 32 + lane);
    }
    hO = fmaxf(hO, 0.f);
    hB = fmaxf(hB, 0.f);
    float vO = hO * __ldg(Wo2 + lane);
    float vB = hB * __ldg(Wb2 + lane);
#pragma unroll
    for (int off = 16; off; off >>= 1) {
        vO += __shfl_down_sync(0xffffffffu, vO, off);
        vB += __shfl_down_sync(0xffffffffu, vB, off);
    }
    if (lane == 0) {
        out[g] = vO + __ldg(bo2);
        out[N_GRAPHS + g] = vB + __ldg(bb2);
    }

    // last-block ticket resets g_s2/g_q2 after every block has read them
    __syncthreads();
    if (threadIdx.x == 0) {
        int old = atomicAdd(&g_ticket, 1);
        if (old == (int)gridDim.x - 1) {
            for (int f = 0; f < HID; f++) { g_s2[f] = 0.f; g_q2[f] = 0.f; }
            g_ticket = 0;
        }
    }
}

// ---------------- launch ----------------
extern "C" void kernel_launch(void* const* d_in, const int* in_sizes, int n_in,
                              void* d_out, int out_size) {
    const float* x      = (const float*)d_in[0];
    const int*   ei     = (const int*)  d_in[1];
    const int*   batch  = (const int*)  d_in[2];
    const float* gfeat  = (const float*)d_in[3];
    const float* W1     = (const float*)d_in[4];
    const float* b1     = (const float*)d_in[5];
    const float* gamma1 = (const float*)d_in[6];
    const float* beta1  = (const float*)d_in[7];
    const float* W2     = (const float*)d_in[8];
    const float* b2     = (const float*)d_in[9];
    const float* gamma2 = (const float*)d_in[10];
    const float* beta2  = (const float*)d_in[11];
    const float* Wo1    = (const float*)d_in[12];
    const float* bo1    = (const float*)d_in[13];
    const float* Wo2    = (const float*)d_in[14];
    const float* bo2    = (const float*)d_in[15];
    const float* Wb1    = (const float*)d_in[16];
    const float* bb1    = (const float*)d_in[17];
    const float* Wb2    = (const float*)d_in[18];
    const float* bb2    = (const float*)d_in[19];
    float* out = (float*)d_out;

    float* s1; float* q1; float* s2; float* q2;
    cudaGetSymbolAddress((void**)&s1, g_s1);
    cudaGetSymbolAddress((void**)&q1, g_q1);
    cudaGetSymbolAddress((void**)&s2, g_s2);
    cudaGetSymbolAddress((void**)&q2, g_q2);
    __half2* a1; __half2* z1; __half2* a2; __half2* z2;
    cudaGetSymbolAddress((void**)&a1, g_a1);
    cudaGetSymbolAddress((void**)&z1, g_z1);
    cudaGetSymbolAddress((void**)&a2, g_a2);
    cudaGetSymbolAddress((void**)&z2, g_z2);

    deg_kernel<<<2048, 256>>>(ei, batch);       // 0
    scan_kernel<<<512, 256>>>(x);               // 1
    bucket_kernel<<<2048, 256>>>(ei);           // 2
    agg1_kernel<<<2048, 256>>>();               // 3  <- ncu capture slot
    xw_kernel<F_IN><<<N_NODES / 128, 128>>>(a1, z1, W1, b1, s1, q1);   // 4
    prep2_kernel<<<4096, 256>>>(gamma1, beta1); // 5
    agg2_kernel<<<2048, 256>>>();               // 6
    xw_kernel<HID><<<N_NODES / 128, 128>>>(a2, z2, W2, b2, s2, q2);    // 7
    poolmlp_kernel<<<128, 256>>>(gamma2, beta2, gfeat, Wo1, bo1, Wo2, bo2,
                                 Wb1, bb1, Wb2, bb2, out);             // 8
}

// round 17
// speedup vs baseline: 1.5387x; 1.0093x over previous
#include <cuda_runtime.h>
#include <cuda_fp16.h>
#include <cstdint>

#define N_NODES  131072
#define N_EDGES  2097152
#define F_IN     32
#define HID      64
#define G_FEAT   16
#define N_GRAPHS 1024
#define BN_EPS   1e-5f
#define SRT_CAP  (N_EDGES + 8 * N_NODES)

// ---------------- device scratch (zero-initialized at load; recycled each run) --------
__device__ int   g_degi[N_NODES];          // zeroed by poolmlp (end of each run)
__device__ int   g_rowstart[N_NODES];
__device__ int   g_fill[N_NODES];
__device__ int   g_srt[SRT_CAP];
__device__ unsigned long long g_scanstat[512];  // zeroed by poolmlp
__device__ float g_dinv[N_NODES];
// +1 dummy zero row at index N_NODES (never written; stays zero)
__device__ __align__(16) __half2 g_y1[(size_t)(N_NODES + 1) * 16];  // dinv*x (32 feats)
__device__ __align__(16) __half2 g_a1[(size_t)N_NODES * 16];        // dinv*agg(y1)
__device__ __align__(16) __half2 g_z1[(size_t)N_NODES * 32];        // a1@W1+b1
__device__ __align__(16) __half2 g_y2[(size_t)(N_NODES + 1) * 32];  // dinv*relu(bn(z1))
__device__ __align__(16) __half2 g_a2[(size_t)N_NODES * 32];        // dinv*agg(y2)
__device__ __align__(16) __half2 g_z2[(size_t)N_NODES * 32];        // a2@W2+b2
__device__ float g_s1[HID], g_q1[HID];     // reset by agg2 (after prep2 reads them)
__device__ float g_s2[HID], g_q2[HID];     // reset by poolmlp last-block ticket
__device__ int   g_start[N_GRAPHS + 1];
__device__ int   g_ticket;                 // reset by the same last block

__device__ __forceinline__ unsigned long long ffma2(unsigned long long a,
                                                    unsigned long long b,
                                                    unsigned long long c) {
    unsigned long long d;
    asm("fma.rn.f32x2 %0, %1, %2, %3;" : "=l"(d) : "l"(a), "l"(b), "l"(c));
    return d;
}
__device__ __forceinline__ void redf(float* p, float v) {
    asm volatile("red.global.add.f32 [%0], %1;" :: "l"(p), "f"(v) : "memory");
}

// ---------------- degree (REDG, no return) + graph-start boundaries ----------------
__global__ void deg_kernel(const int* __restrict__ ei, const int* __restrict__ batch) {
    int t = blockIdx.x * 256 + threadIdx.x;       // 524288 threads
    int4 d = __ldg((const int4*)(ei + N_EDGES) + t);
    unsigned one = 1u;
    asm volatile("red.global.add.u32 [%0], %1;" :: "l"((unsigned*)(g_degi + d.x)), "r"(one) : "memory");
    asm volatile("red.global.add.u32 [%0], %1;" :: "l"((unsigned*)(g_degi + d.y)), "r"(one) : "memory");
    asm volatile("red.global.add.u32 [%0], %1;" :: "l"((unsigned*)(g_degi + d.z)), "r"(one) : "memory");
    asm volatile("red.global.add.u32 [%0], %1;" :: "l"((unsigned*)(g_degi + d.w)), "r"(one) : "memory");
    if (t < N_NODES) {
        int b = __ldg(batch + t);
        int prev = (t == 0) ? -1 : __ldg(batch + t - 1);
        for (int g = prev + 1; g <= b; g++) g_start[g] = t;
        if (t == N_NODES - 1)
            for (int g = b + 1; g <= N_GRAPHS; g++) g_start[g] = N_NODES;
    }
}

// ---------------- single-pass scan over PADDED degrees (+self edge) + dinv + y1 ------
__global__ __launch_bounds__(256) void scan_kernel(const float* __restrict__ x) {
    __shared__ int sh[256];
    __shared__ int s_off;
    int tid = threadIdx.x;
    int bid = blockIdx.x;
    int n = bid * 256 + tid;
    int d = g_degi[n];
    int dp = (d + 8) & ~7;          // self edge + pad to multiple of 8
    sh[tid] = dp;
    __syncthreads();
#pragma unroll
    for (int off = 1; off < 256; off <<= 1) {
        int v = (tid >= off) ? sh[tid - off] : 0;
        __syncthreads();
        sh[tid] += v;
        __syncthreads();
    }
    int total = sh[255];
    if (tid == 0) {
        if (bid == 0) {
            atomicExch(&g_scanstat[0], (2ull << 32) | (unsigned)total);
            s_off = 0;
        } else {
            atomicExch(&g_scanstat[bid], (1ull << 32) | (unsigned)total);
            long long running = 0;
            int p = bid - 1;
            while (p >= 0) {
                unsigned long long st;
                do { st = atomicAdd(&g_scanstat[p], 0ull); } while ((st >> 32) == 0ull);
                running += (unsigned)st;
                if ((st >> 32) == 2ull) break;
                p--;
            }
            atomicExch(&g_scanstat[bid], (2ull << 32) | (unsigned)(running + total));
            s_off = (int)running;
        }
    }
    __syncthreads();
    int rs = s_off + sh[tid] - dp;   // exclusive prefix (padded)
    g_rowstart[n] = rs;
    g_fill[n] = rs;
    g_srt[rs + d] = n;                                     // self edge
    for (int p = d + 1; p < dp; p++) g_srt[rs + p] = N_NODES;  // dummy zero rows
    float dv = rsqrtf((float)d + 1.0f);
    g_dinv[n] = dv;
    const float4* xr = (const float4*)(x + (size_t)n * F_IN);
    uint4* yw = (uint4*)(g_y1 + (size_t)n * 16);
#pragma unroll
    for (int q = 0; q < 2; q++) {
        float4 v0 = __ldg(xr + 4 * q + 0);
        float4 v1 = __ldg(xr + 4 * q + 1);
        float4 v2 = __ldg(xr + 4 * q + 2);
        float4 v3 = __ldg(xr + 4 * q + 3);
        __half2 h0 = __floats2half2_rn(v0.x * dv, v0.y * dv);
        __half2 h1 = __floats2half2_rn(v0.z * dv, v0.w * dv);
        __half2 h2 = __floats2half2_rn(v1.x * dv, v1.y * dv);
        __half2 h3 = __floats2half2_rn(v1.z * dv, v1.w * dv);
        __half2 h4 = __floats2half2_rn(v2.x * dv, v2.y * dv);
        __half2 h5 = __floats2half2_rn(v2.z * dv, v2.w * dv);
        __half2 h6 = __floats2half2_rn(v3.x * dv, v3.y * dv);
        __half2 h7 = __floats2half2_rn(v3.z * dv, v3.w * dv);
        uint4 w0, w1;
        w0.x = *(unsigned*)&h0; w0.y = *(unsigned*)&h1;
        w0.z = *(unsigned*)&h2; w0.w = *(unsigned*)&h3;
        w1.x = *(unsigned*)&h4; w1.y = *(unsigned*)&h5;
        w1.z = *(unsigned*)&h6; w1.w = *(unsigned*)&h7;
        yw[2 * q + 0] = w0;
        yw[2 * q + 1] = w1;
    }
}

// ---------------- bucket edges by dst (vectorized atomic fill) ----------------
__global__ void bucket_kernel(const int* __restrict__ ei) {
    int e4 = blockIdx.x * 256 + threadIdx.x;
    int4 s = __ldg((const int4*)ei + e4);
    int4 d = __ldg((const int4*)(ei + N_EDGES) + e4);
    g_srt[atomicAdd(&g_fill[d.x], 1)] = s.x;
    g_srt[atomicAdd(&g_fill[d.y], 1)] = s.y;
    g_srt[atomicAdd(&g_fill[d.z], 1)] = s.z;
    g_srt[atomicAdd(&g_fill[d.w], 1)] = s.w;
}

// ---------------- CSR aggregate, layer 1: 8 nodes/warp, 4 lanes/node, LDG.128 -------
// Each gather instruction covers 8 rows x 64B = 512B (max density).
__global__ __launch_bounds__(256) void agg1_kernel() {
    int warp = blockIdx.x * 8 + (threadIdx.x >> 5);
    int lane = threadIdx.x & 31;
    int sub = lane >> 2;        // node subgroup 0..7
    int sl = lane & 3;          // uint4 slice (4 per 64B row)
    const uint4* yb = (const uint4*)g_y1;   // 4 uint4 per row
    int n = warp * 8 + sub;
    int rs = __ldg(&g_rowstart[n]);
    int degp = (__ldg(&g_degi[n]) + 8) & ~7;   // includes self + pad
    int mx = degp;
    mx = max(mx, __shfl_xor_sync(0xffffffffu, mx, 4));
    mx = max(mx, __shfl_xor_sync(0xffffffffu, mx, 8));
    mx = max(mx, __shfl_xor_sync(0xffffffffu, mx, 16));
    __half2 zz = __float2half2_rn(0.f);
    __half2 a0 = zz, a1 = zz, a2 = zz, a3 = zz;
    __half2 b0 = zz, b1 = zz, b2 = zz, b3 = zz;
    for (int base = 0; base < mx; base += 4) {
        int idx = (base < degp) ? __ldg(&g_srt[rs + base + sl]) : (int)N_NODES;
        int j0 = __shfl_sync(0xffffffffu, idx, (sub << 2) + 0);
        int j1 = __shfl_sync(0xffffffffu, idx, (sub << 2) + 1);
        int j2 = __shfl_sync(0xffffffffu, idx, (sub << 2) + 2);
        int j3 = __shfl_sync(0xffffffffu, idx, (sub << 2) + 3);
        uint4 u0 = __ldg(yb + (size_t)j0 * 4 + sl);
        uint4 u1 = __ldg(yb + (size_t)j1 * 4 + sl);
        uint4 u2 = __ldg(yb + (size_t)j2 * 4 + sl);
        uint4 u3 = __ldg(yb + (size_t)j3 * 4 + sl);
        a0 = __hadd2(a0, *(__half2*)&u0.x);
        a1 = __hadd2(a1, *(__half2*)&u0.y);
        a2 = __hadd2(a2, *(__half2*)&u0.z);
        a3 = __hadd2(a3, *(__half2*)&u0.w);
        b0 = __hadd2(b0, *(__half2*)&u1.x);
        b1 = __hadd2(b1, *(__half2*)&u1.y);
        b2 = __hadd2(b2, *(__half2*)&u1.z);
        b3 = __hadd2(b3, *(__half2*)&u1.w);
        a0 = __hadd2(a0, *(__half2*)&u2.x);
        a1 = __hadd2(a1, *(__half2*)&u2.y);
        a2 = __hadd2(a2, *(__half2*)&u2.z);
        a3 = __hadd2(a3, *(__half2*)&u2.w);
        b0 = __hadd2(b0, *(__half2*)&u3.x);
        b1 = __hadd2(b1, *(__half2*)&u3.y);
        b2 = __hadd2(b2, *(__half2*)&u3.z);
        b3 = __hadd2(b3, *(__half2*)&u3.w);
    }
    a0 = __hadd2(a0, b0);
    a1 = __hadd2(a1, b1);
    a2 = __hadd2(a2, b2);
    a3 = __hadd2(a3, b3);
    __half2 hd = __float2half2_rn(__ldg(&g_dinv[n]));
    a0 = __hmul2(a0, hd);
    a1 = __hmul2(a1, hd);
    a2 = __hmul2(a2, hd);
    a3 = __hmul2(a3, hd);
    uint4 o;
    o.x = *(unsigned*)&a0; o.y = *(unsigned*)&a1;
    o.z = *(unsigned*)&a2; o.w = *(unsigned*)&a3;
    *((uint4*)g_a1 + (size_t)n * 4 + sl) = o;
}

// ---------------- CSR aggregate, layer 2: 4 nodes/warp, 8 lanes/node ---------------
// (already 512B/instr) Dual banks + pipelined index; also resets g_s1/g_q1.
__global__ __launch_bounds__(256) void agg2_kernel() {
    if (blockIdx.x == 0 && threadIdx.x < HID) {
        g_s1[threadIdx.x] = 0.f;
        g_q1[threadIdx.x] = 0.f;
    }
    int warp = blockIdx.x * 8 + (threadIdx.x >> 5);
    int lane = threadIdx.x & 31;
    int sub = lane >> 3;        // node subgroup 0..3
    int sl = lane & 7;          // 16B slice (8 per 128B row)
    const uint4* yb = (const uint4*)g_y2;   // 8 uint4 per row
#pragma unroll
    for (int rep = 0; rep < 2; rep++) {
        int n = warp * 8 + rep * 4 + sub;
        int rs = __ldg(&g_rowstart[n]);
        int degp = (__ldg(&g_degi[n]) + 8) & ~7;   // includes self + pad
        int mx = degp;
        mx = max(mx, __shfl_xor_sync(0xffffffffu, mx, 8));
        mx = max(mx, __shfl_xor_sync(0xffffffffu, mx, 16));
        __half2 zz = __float2half2_rn(0.f);
        __half2 a0 = zz, a1 = zz, a2 = zz, a3 = zz;
        __half2 b0 = zz, b1 = zz, b2 = zz, b3 = zz;
        int idx = __ldg(&g_srt[rs + sl]);
        for (int base = 0; base < mx; base += 8) {
            int nb = base + 8;
            int idxn = 0;
            if (nb < mx) idxn = (nb < degp) ? __ldg(&g_srt[rs + nb + sl]) : (int)N_NODES;
#pragma unroll
            for (int p = 0; p < 8; p += 2) {
                int j0 = __shfl_sync(0xffffffffu, idx, (sub << 3) + p);
                int j1 = __shfl_sync(0xffffffffu, idx, (sub << 3) + p + 1);
                uint4 u0 = __ldg(yb + (size_t)j0 * 8 + sl);
                uint4 u1 = __ldg(yb + (size_t)j1 * 8 + sl);
                a0 = __hadd2(a0, *(__half2*)&u0.x);
                a1 = __hadd2(a1, *(__half2*)&u0.y);
                a2 = __hadd2(a2, *(__half2*)&u0.z);
                a3 = __hadd2(a3, *(__half2*)&u0.w);
                b0 = __hadd2(b0, *(__half2*)&u1.x);
                b1 = __hadd2(b1, *(__half2*)&u1.y);
                b2 = __hadd2(b2, *(__half2*)&u1.z);
                b3 = __hadd2(b3, *(__half2*)&u1.w);
            }
            idx = idxn;
        }
        a0 = __hadd2(a0, b0);
        a1 = __hadd2(a1, b1);
        a2 = __hadd2(a2, b2);
        a3 = __hadd2(a3, b3);
        __half2 hd = __float2half2_rn(__ldg(&g_dinv[n]));
        a0 = __hmul2(a0, hd);
        a1 = __hmul2(a1, hd);
        a2 = __hmul2(a2, hd);
        a3 = __hmul2(a3, hd);
        uint4 o;
        o.x = *(unsigned*)&a0; o.y = *(unsigned*)&a1;
        o.z = *(unsigned*)&a2; o.w = *(unsigned*)&a3;
        *((uint4*)g_a2 + (size_t)n * 8 + sl) = o;
    }
}

// ---------------- GEMM: z = a @ W + b ; fused BN stats ----------------
template <int K>
__global__ __launch_bounds__(128) void xw_kernel(const __half2* __restrict__ av,
                                                 __half2* __restrict__ zv,
                                                 const float* __restrict__ W,
                                                 const float* __restrict__ b,
                                                 float* __restrict__ sArr,
                                                 float* __restrict__ qArr) {
    __shared__ __align__(16) float sW[K * HID];
    __shared__ __half2 sOut[128][33];
    __shared__ float ps[4][64], pq[4][64];
    int tid = threadIdx.x;
    for (int i = tid; i < K * HID; i += 128) sW[i] = W[i];
    __syncthreads();
    int n = blockIdx.x * 128 + tid;
    float in[K];
    {
        const uint4* r = (const uint4*)(av + (size_t)n * (K / 2));
#pragma unroll
        for (int q = 0; q < K / 8; q++) {
            uint4 u = __ldg(r + q);
            unsigned uu[4] = {u.x, u.y, u.z, u.w};
#pragma unroll
            for (int m = 0; m < 4; m++) {
                float2 f = __half22float2(*(__half2*)&uu[m]);
                in[8 * q + 2 * m + 0] = f.x;
                in[8 * q + 2 * m + 1] = f.y;
            }
        }
    }
#pragma unroll 1
    for (int jb = 0; jb < 4; jb++) {
        unsigned long long acc[8];
#pragma unroll
        for (int m = 0; m < 8; m++) acc[m] = 0ull;
#pragma unroll 4
        for (int k = 0; k < K; k++) {
            unsigned long long xp;
            asm("mov.b64 %0, {%1, %1};" : "=l"(xp) : "r"(__float_as_uint(in[k])));
            const ulonglong2* wp = (const ulonglong2*)(sW + k * HID + jb * 16);
            ulonglong2 w01 = wp[0], w23 = wp[1], w45 = wp[2], w67 = wp[3];
            acc[0] = ffma2(xp, w01.x, acc[0]);
            acc[1] = ffma2(xp, w01.y, acc[1]);
            acc[2] = ffma2(xp, w23.x, acc[2]);
            acc[3] = ffma2(xp, w23.y, acc[3]);
            acc[4] = ffma2(xp, w45.x, acc[4]);
            acc[5] = ffma2(xp, w45.y, acc[5]);
            acc[6] = ffma2(xp, w67.x, acc[6]);
            acc[7] = ffma2(xp, w67.y, acc[7]);
        }
#pragma unroll
        for (int m = 0; m < 8; m++) {
            float lo, hi;
            asm("mov.b64 {%0, %1}, %2;" : "=f"(lo), "=f"(hi) : "l"(acc[m]));
            int f0 = jb * 16 + 2 * m;
            sOut[tid][jb * 8 + m] = __floats2half2_rn(lo + __ldg(b + f0),
                                                      hi + __ldg(b + f0 + 1));
        }
    }
    __syncthreads();
    unsigned* dst = (unsigned*)(zv + (size_t)blockIdx.x * 128 * 32);
    const unsigned* srcBase = (const unsigned*)sOut;
#pragma unroll
    for (int i = tid; i < 4096; i += 128) {
        int node = i >> 5, c = i & 31;
        dst[i] = srcBase[node * 33 + c];
    }
    {
        int c = tid & 31, part = tid >> 5;
        float s0 = 0.f, s1 = 0.f, q0 = 0.f, q1 = 0.f;
#pragma unroll 4
        for (int m = 0; m < 32; m++) {
            float2 f = __half22float2(sOut[part * 32 + m][c]);
            s0 += f.x; s1 += f.y; q0 += f.x * f.x; q1 += f.y * f.y;
        }
        ps[part][2 * c] = s0; ps[part][2 * c + 1] = s1;
        pq[part][2 * c] = q0; pq[part][2 * c + 1] = q1;
    }
    __syncthreads();
    if (tid < 64) {
        float s = ps[0][tid] + ps[1][tid] + ps[2][tid] + ps[3][tid];
        float q = pq[0][tid] + pq[1][tid] + pq[2][tid] + pq[3][tid];
        redf(sArr + tid, s);
        redf(qArr + tid, q);
    }
}

// ---------------- prep2: y2 = fp16(dinv * relu(bn1(z1))) ----------------
__global__ __launch_bounds__(256) void prep2_kernel(const float* __restrict__ gamma,
                                                    const float* __restrict__ beta) {
    __shared__ float sc[HID], sh[HID];
    int tid = threadIdx.x;
    if (tid < HID) {
        const float inv_n = 1.0f / (float)N_NODES;
        float mu = g_s1[tid] * inv_n;
        float var = g_q1[tid] * inv_n - mu * mu;
        float rstd = rsqrtf(var + BN_EPS);
        float s = rstd * __ldg(gamma + tid);
        sc[tid] = s;
        sh[tid] = __ldg(beta + tid) - mu * s;
    }
    __syncthreads();
    int i4 = blockIdx.x * 256 + tid;
    int n = i4 >> 3;
    int fb = (i4 & 7) * 8;
    float d = __ldg(&g_dinv[n]);
    uint4 u = *((const uint4*)g_z1 + i4);
    unsigned uu[4] = {u.x, u.y, u.z, u.w};
    uint4 o;
    unsigned* oo = (unsigned*)&o;
#pragma unroll
    for (int m = 0; m < 4; m++) {
        float2 f = __half22float2(*(__half2*)&uu[m]);
        int f0 = fb + 2 * m;
        float y0 = fmaxf(f.x * sc[f0] + sh[f0], 0.f) * d;
        float y1 = fmaxf(f.y * sc[f0 + 1] + sh[f0 + 1], 0.f) * d;
        __half2 h = __floats2half2_rn(y0, y1);
        oo[m] = *(unsigned*)&h;
    }
    *((uint4*)g_y2 + i4) = o;
}

// ---------------- fused pool + MLP heads + state recycling ----------------
__global__ __launch_bounds__(256) void poolmlp_kernel(
    const float* __restrict__ gamma, const float* __restrict__ beta,
    const float* __restrict__ gf,
    const float* __restrict__ Wo1, const float* __restrict__ bo1,
    const float* __restrict__ Wo2, const float* __restrict__ bo2,
    const float* __restrict__ Wb1, const float* __restrict__ bb1,
    const float* __restrict__ Wb2, const float* __restrict__ bb2,
    float* __restrict__ out) {
    int g = (blockIdx.x * 256 + threadIdx.x) >> 5;
    int lane = threadIdx.x & 31;
    int s = g_start[g], e = g_start[g + 1];
    int c = e - s;
    const float inv_n = 1.0f / (float)N_NODES;
    int f0 = 2 * lane, f1 = 2 * lane + 1;
    float mu0 = g_s2[f0] * inv_n, mu1 = g_s2[f1] * inv_n;
    float v0 = g_q2[f0] * inv_n - mu0 * mu0;
    float v1 = g_q2[f1] * inv_n - mu1 * mu1;
    float sc0 = rsqrtf(v0 + BN_EPS) * __ldg(gamma + f0);
    float sc1 = rsqrtf(v1 + BN_EPS) * __ldg(gamma + f1);
    float sh0 = __ldg(beta + f0) - mu0 * sc0;
    float sh1 = __ldg(beta + f1) - mu1 * sc1;

    // recycle state not read by this kernel: g_degi, g_scanstat
    {
        int t = blockIdx.x * 256 + threadIdx.x;       // 32768 threads
        uint4 zz = make_uint4(0u, 0u, 0u, 0u);
        *((uint4*)g_degi + t) = zz;                    // 131072 ints = 32768 uint4
        if (t < 512) g_scanstat[t] = 0ull;
    }

    float s0 = 0.f, s1 = 0.f;
    int i = s;
    for (; i + 4 <= e; i += 4) {
        float2 a0 = __half22float2(g_z2[(size_t)(i + 0) * 32 + lane]);
        float2 a1 = __half22float2(g_z2[(size_t)(i + 1) * 32 + lane]);
        float2 a2 = __half22float2(g_z2[(size_t)(i + 2) * 32 + lane]);
        float2 a3 = __half22float2(g_z2[(size_t)(i + 3) * 32 + lane]);
        s0 += fmaxf(a0.x * sc0 + sh0, 0.f) + fmaxf(a1.x * sc0 + sh0, 0.f)
            + fmaxf(a2.x * sc0 + sh0, 0.f) + fmaxf(a3.x * sc0 + sh0, 0.f);
        s1 += fmaxf(a0.y * sc1 + sh1, 0.f) + fmaxf(a1.y * sc1 + sh1, 0.f)
            + fmaxf(a2.y * sc1 + sh1, 0.f) + fmaxf(a3.y * sc1 + sh1, 0.f);
    }
    for (; i < e; i++) {
        float2 f = __half22float2(g_z2[(size_t)i * 32 + lane]);
        s0 += fmaxf(f.x * sc0 + sh0, 0.f);
        s1 += fmaxf(f.y * sc1 + sh1, 0.f);
    }
    float inv = (c > 0) ? 1.0f / (float)c : 0.f;
    float p0 = s0 * inv, p1 = s1 * inv;

    // heads: hidden unit = lane (32 units)
    float hO = __ldg(bo1 + lane), hB = __ldg(bb1 + lane);
#pragma unroll 8
    for (int i2 = 0; i2 < 32; i2++) {
        float c0 = __shfl_sync(0xffffffffu, p0, i2);
        float c1 = __shfl_sync(0xffffffffu, p1, i2);
        hO += c0 * __ldg(Wo1 + (2 * i2) * 32 + lane) + c1 * __ldg(Wo1 + (2 * i2 + 1) * 32 + lane);
        hB += c0 * __ldg(Wb1 + (2 * i2) * 32 + lane) + c1 * __ldg(Wb1 + (2 * i2 + 1) * 32 + lane);
    }
#pragma unroll
    for (int i3 = 0; i3 < G_FEAT; i3++) {
        float ci = __ldg(gf + (size_t)g * G_FEAT + i3);
        hO += ci * __ldg(Wo1 + (HID + i3) * 32 + lane);
        hB += ci * __ldg(Wb1 + (HID + i3) * 32 + lane);
    }
    hO = fmaxf(hO, 0.f);
    hB = fmaxf(hB, 0.f);
    float vO = hO * __ldg(Wo2 + lane);
    float vB = hB * __ldg(Wb2 + lane);
#pragma unroll
    for (int off = 16; off; off >>= 1) {
        vO += __shfl_down_sync(0xffffffffu, vO, off);
        vB += __shfl_down_sync(0xffffffffu, vB, off);
    }
    if (lane == 0) {
        out[g] = vO + __ldg(bo2);
        out[N_GRAPHS + g] = vB + __ldg(bb2);
    }

    // last-block ticket resets g_s2/g_q2 after every block has read them
    __syncthreads();
    if (threadIdx.x == 0) {
        int old = atomicAdd(&g_ticket, 1);
        if (old == (int)gridDim.x - 1) {
            for (int f = 0; f < HID; f++) { g_s2[f] = 0.f; g_q2[f] = 0.f; }
            g_ticket = 0;
        }
    }
}

// ---------------- launch ----------------
extern "C" void kernel_launch(void* const* d_in, const int* in_sizes, int n_in,
                              void* d_out, int out_size) {
    const float* x      = (const float*)d_in[0];
    const int*   ei     = (const int*)  d_in[1];
    const int*   batch  = (const int*)  d_in[2];
    const float* gfeat  = (const float*)d_in[3];
    const float* W1     = (const float*)d_in[4];
    const float* b1     = (const float*)d_in[5];
    const float* gamma1 = (const float*)d_in[6];
    const float* beta1  = (const float*)d_in[7];
    const float* W2     = (const float*)d_in[8];
    const float* b2     = (const float*)d_in[9];
    const float* gamma2 = (const float*)d_in[10];
    const float* beta2  = (const float*)d_in[11];
    const float* Wo1    = (const float*)d_in[12];
    const float* bo1    = (const float*)d_in[13];
    const float* Wo2    = (const float*)d_in[14];
    const float* bo2    = (const float*)d_in[15];
    const float* Wb1    = (const float*)d_in[16];
    const float* bb1    = (const float*)d_in[17];
    const float* Wb2    = (const float*)d_in[18];
    const float* bb2    = (const float*)d_in[19];
    float* out = (float*)d_out;

    float* s1; float* q1; float* s2; float* q2;
    cudaGetSymbolAddress((void**)&s1, g_s1);
    cudaGetSymbolAddress((void**)&q1, g_q1);
    cudaGetSymbolAddress((void**)&s2, g_s2);
    cudaGetSymbolAddress((void**)&q2, g_q2);
    __half2* a1; __half2* z1; __half2* a2; __half2* z2;
    cudaGetSymbolAddress((void**)&a1, g_a1);
    cudaGetSymbolAddress((void**)&z1, g_z1);
    cudaGetSymbolAddress((void**)&a2, g_a2);
    cudaGetSymbolAddress((void**)&z2, g_z2);

    deg_kernel<<<2048, 256>>>(ei, batch);       // 0
    scan_kernel<<<512, 256>>>(x);               // 1
    bucket_kernel<<<2048, 256>>>(ei);           // 2
    agg1_kernel<<<2048, 256>>>();               // 3  <- ncu capture slot
    xw_kernel<F_IN><<<N_NODES / 128, 128>>>(a1, z1, W1, b1, s1, q1);   // 4
    prep2_kernel<<<4096, 256>>>(gamma1, beta1); // 5
    agg2_kernel<<<2048, 256>>>();               // 6
    xw_kernel<HID><<<N_NODES / 128, 128>>>(a2, z2, W2, b2, s2, q2);    // 7
    poolmlp_kernel<<<128, 256>>>(gamma2, beta2, gfeat, Wo1, bo1, Wo2, bo2,
                                 Wb1, bb1, Wb2, bb2, out);             // 8
}